// round 3
// baseline (speedup 1.0000x reference)
#include <cuda_runtime.h>
#include <math.h>

#define NBIG (8*64*128*128)
#define EPSF 1e-5f

// ---------------- scratch buffers (device globals; no allocation) ----------
__device__ float g_kse1[NBIG];   // 1 + bilinear_upsample(k)
__device__ float g_fuse[NBIG];   // fuseadd (already *(1+kse))
__device__ float g_f1[NBIG];
__device__ float g_f2[NBIG];
__device__ float g_eadd[NBIG];
__device__ float g_A1[NBIG];
__device__ float g_out1[NBIG];   // scaled by (1+kse)
__device__ float g_out2[NBIG];   // multidil, scaled
__device__ float g_o2c[NBIG];    // out2conv
__device__ float g_fo2[NBIG];    // fuseout2
__device__ float g_eo2[NBIG];    // eout2
__device__ float g_o2f[NBIG];    // final out2 (post conv5)
__device__ float g_t1[NBIG];     // after conv0a
__device__ float g_t2[NBIG];     // after conv0b
__device__ float g_va[1024];     // mean of x1 per (b, cin)  8*128
__device__ float g_fb[512];      // fusebase per (b, c)
__device__ float g_am[512];      // mean sigmoid(fuse)
__device__ float g_ses[512];     // SE scale

__device__ __forceinline__ float leakyf(float x) { return x >= 0.f ? x : 0.01f * x; }
__device__ __forceinline__ float sigmoidf(float x) { return 1.f / (1.f + expf(-x)); }

__device__ __forceinline__ float blockReduceSum(float v) {
    __shared__ float sh[32];
    int lane = threadIdx.x & 31, wid = threadIdx.x >> 5;
    #pragma unroll
    for (int o = 16; o; o >>= 1) v += __shfl_down_sync(0xffffffffu, v, o);
    if (lane == 0) sh[wid] = v;
    __syncthreads();
    v = (threadIdx.x < (blockDim.x >> 5)) ? sh[lane] : 0.f;
    if (wid == 0) {
        #pragma unroll
        for (int o = 16; o; o >>= 1) v += __shfl_down_sync(0xffffffffu, v, o);
    }
    return v;  // valid in thread 0
}

// ---------------- small kernels -------------------------------------------
// mean over HW per (b, cin): 1024 rows of 16384
__global__ __launch_bounds__(256) void rowmean_k(const float* __restrict__ x, float* __restrict__ out) {
    int row = blockIdx.x;
    const float* p = x + ((size_t)row << 14);
    float s = 0.f;
    for (int i = threadIdx.x; i < 16384; i += 256) s += p[i];
    s = blockReduceSum(s);
    if (threadIdx.x == 0) out[row] = s * (1.f / 16384.f);
}

// mean over HW of sigmoid(fuse) per (b, c): 512 rows
__global__ __launch_bounds__(256) void attmean_k(const float* __restrict__ x, float* __restrict__ out) {
    int row = blockIdx.x;
    const float* p = x + ((size_t)row << 14);
    float s = 0.f;
    for (int i = threadIdx.x; i < 16384; i += 256) s += sigmoidf(p[i]);
    s = blockReduceSum(s);
    if (threadIdx.x == 0) out[row] = s * (1.f / 16384.f);
}

// fusebase[b][c] = dot(conv_w[c], va[b]) + 2*bias[c]
__global__ void fusebase_k(const float* __restrict__ va, const float* __restrict__ cw,
                           const float* __restrict__ bias, float* __restrict__ fb) {
    int t = threadIdx.x;  // 512
    int b = t >> 6, c = t & 63;
    float s = 0.f;
    for (int i = 0; i < 128; i++) s += cw[c * 128 + i] * va[b * 128 + i];
    fb[t] = s + 2.f * bias[c];
}

// SE: z = leaky(am @ w1^T); ses = sigmoid(z @ w2^T)
__global__ void se_k(const float* __restrict__ am, const float* __restrict__ w1,
                     const float* __restrict__ w2, float* __restrict__ ses) {
    __shared__ float z[8][4];
    int t = threadIdx.x;  // 512
    if (t < 32) {
        int b = t >> 2, j = t & 3;
        float s = 0.f;
        for (int c = 0; c < 64; c++) s += w1[j * 64 + c] * am[b * 64 + c];
        z[b][j] = leakyf(s);
    }
    __syncthreads();
    int b = t >> 6, c = t & 63;
    float s = 0.f;
    #pragma unroll
    for (int j = 0; j < 4; j++) s += z[b][j] * w2[c * 4 + j];
    ses[t] = sigmoidf(s);
}

// kse1 = 1 + bilinear_align_corners(k, 5x5 -> 128x128)
__global__ __launch_bounds__(256) void kse_k(const float* __restrict__ k, float* __restrict__ out) {
    int idx = blockIdx.x * 256 + threadIdx.x;
    int w = idx & 127, h = (idx >> 7) & 127, bc = idx >> 14;
    const float st = 4.0f / 127.0f;
    float ys = h * st, xs = w * st;
    int y0 = (int)floorf(ys); if (y0 > 4) y0 = 4; if (y0 < 0) y0 = 0;
    int x0 = (int)floorf(xs); if (x0 > 4) x0 = 4; if (x0 < 0) x0 = 0;
    int y1 = min(y0 + 1, 4), x1 = min(x0 + 1, 4);
    float wy = ys - (float)y0, wx = xs - (float)x0;
    const float* kb = k + bc * 25;
    float r0 = kb[y0 * 5 + x0] * (1.f - wx) + kb[y0 * 5 + x1] * wx;
    float r1 = kb[y1 * 5 + x0] * (1.f - wx) + kb[y1 * 5 + x1] * wx;
    out[idx] = 1.f + (r0 * (1.f - wy) + r1 * wy);
}

// final: out = sigmoid(fuse) * ses * t2 * A1
__global__ __launch_bounds__(256) void final_k(const float* __restrict__ fuse, const float* __restrict__ ses,
                                               const float* __restrict__ t2, const float* __restrict__ A1,
                                               float* __restrict__ out) {
    int idx = blockIdx.x * 256 + threadIdx.x;
    int bc = idx >> 14;
    out[idx] = sigmoidf(fuse[idx]) * ses[bc] * t2[idx] * A1[idx];
}

// ---------------- 1x1 convs as SGEMM --------------------------------------
// Triple: rows 0..63 -> fuseadd path (conv_w), 64..127 -> f1 (conv1), 128..191 -> f2 (conv2)
__global__ __launch_bounds__(256) void g1x1_triple_k(
    const float* __restrict__ x1,
    const float* __restrict__ wf, const float* __restrict__ w1c,
    const float* __restrict__ g1, const float* __restrict__ b1,
    const float* __restrict__ w2c, const float* __restrict__ g2, const float* __restrict__ b2,
    const float* __restrict__ fb, const float* __restrict__ kse1,
    float* __restrict__ ofuse, float* __restrict__ of1, float* __restrict__ of2) {
    __shared__ float As[16][68];
    __shared__ float Bs[16][64];
    int convid = blockIdx.y, b = blockIdx.z, n0 = blockIdx.x * 64;
    const float* W = convid == 0 ? wf : (convid == 1 ? w1c : w2c);
    int tid = threadIdx.x, ty = tid >> 4, tx = tid & 15;
    float acc[4][4] = {};
    for (int k0 = 0; k0 < 128; k0 += 16) {
        __syncthreads();
        {
            int m = tid >> 2, kq = (tid & 3) * 4;
            float4 a4 = *reinterpret_cast<const float4*>(W + m * 128 + k0 + kq);
            As[kq + 0][m] = a4.x; As[kq + 1][m] = a4.y; As[kq + 2][m] = a4.z; As[kq + 3][m] = a4.w;
        }
        #pragma unroll
        for (int l = 0; l < 4; l++) {
            int e = tid + l * 256, kk = e >> 6, n = e & 63;
            Bs[kk][n] = x1[((b * 128 + k0 + kk) << 14) + n0 + n];
        }
        __syncthreads();
        #pragma unroll
        for (int kk = 0; kk < 16; kk++) {
            float4 a = *reinterpret_cast<const float4*>(&As[kk][ty * 4]);
            float4 bv = *reinterpret_cast<const float4*>(&Bs[kk][tx * 4]);
            float av[4] = {a.x, a.y, a.z, a.w};
            float bb[4] = {bv.x, bv.y, bv.z, bv.w};
            #pragma unroll
            for (int i = 0; i < 4; i++)
                #pragma unroll
                for (int j = 0; j < 4; j++) acc[i][j] += av[i] * bb[j];
        }
    }
    const float rs = rsqrtf(1.f + EPSF);
    #pragma unroll
    for (int i = 0; i < 4; i++) {
        int c = ty * 4 + i;
        #pragma unroll
        for (int j = 0; j < 4; j++) {
            int idx = ((b * 64 + c) << 14) + n0 + tx * 4 + j;
            if (convid == 0) {
                float v = acc[i][j] + fb[b * 64 + c];
                ofuse[idx] = v * kse1[idx];
            } else if (convid == 1) {
                of1[idx] = leakyf(acc[i][j] * (g1[c] * rs) + b1[c]);
            } else {
                of2[idx] = leakyf(acc[i][j] * (g2[c] * rs) + b2[c]);
            }
        }
    }
}

// conv0a: 1x1 over concat(out1, out2f) (128 in), bnlrelu
__global__ __launch_bounds__(256) void g1x1_cat_k(
    const float* __restrict__ p1, const float* __restrict__ p2,
    const float* __restrict__ W, const float* __restrict__ gg, const float* __restrict__ bb,
    float* __restrict__ out) {
    __shared__ float As[16][68];
    __shared__ float Bs[16][64];
    int b = blockIdx.z, n0 = blockIdx.x * 64;
    int tid = threadIdx.x, ty = tid >> 4, tx = tid & 15;
    float acc[4][4] = {};
    for (int k0 = 0; k0 < 128; k0 += 16) {
        __syncthreads();
        {
            int m = tid >> 2, kq = (tid & 3) * 4;
            float4 a4 = *reinterpret_cast<const float4*>(W + m * 128 + k0 + kq);
            As[kq + 0][m] = a4.x; As[kq + 1][m] = a4.y; As[kq + 2][m] = a4.z; As[kq + 3][m] = a4.w;
        }
        #pragma unroll
        for (int l = 0; l < 4; l++) {
            int e = tid + l * 256, kk = e >> 6, n = e & 63;
            int ic = k0 + kk;
            const float* src = (ic < 64) ? (p1 + ((b * 64 + ic) << 14))
                                         : (p2 + ((b * 64 + ic - 64) << 14));
            Bs[kk][n] = src[n0 + n];
        }
        __syncthreads();
        #pragma unroll
        for (int kk = 0; kk < 16; kk++) {
            float4 a = *reinterpret_cast<const float4*>(&As[kk][ty * 4]);
            float4 bv = *reinterpret_cast<const float4*>(&Bs[kk][tx * 4]);
            float av[4] = {a.x, a.y, a.z, a.w};
            float bvv[4] = {bv.x, bv.y, bv.z, bv.w};
            #pragma unroll
            for (int i = 0; i < 4; i++)
                #pragma unroll
                for (int j = 0; j < 4; j++) acc[i][j] += av[i] * bvv[j];
        }
    }
    const float rs = rsqrtf(1.f + EPSF);
    #pragma unroll
    for (int i = 0; i < 4; i++) {
        int c = ty * 4 + i;
        float s = gg[c] * rs, beta = bb[c];
        #pragma unroll
        for (int j = 0; j < 4; j++) {
            int idx = ((b * 64 + c) << 14) + n0 + tx * 4 + j;
            out[idx] = leakyf(acc[i][j] * s + beta);
        }
    }
}

// ---------------- direct conv (64->64, KS=3 or 5), fused epilogues --------
// MODE 0: bnlrelu
// MODE 1: sigmoid(bnlrelu)
// MODE 2: bnlrelu * aux1                (out1 * (1+kse))
// MODE 3: sigmoid(bnlrelu)*aux1*aux2    (A2 * A1 * out2conv)
// MODE 4: bnlrelu + aux1 + aux2         (eout2)
template <int KS, int MODE>
__global__ __launch_bounds__(256) void conv_k(
    const float* __restrict__ in, const float* __restrict__ w,
    const float* __restrict__ gg, const float* __restrict__ bb,
    const float* __restrict__ aux1, const float* __restrict__ aux2,
    float* __restrict__ out) {
    constexpr int PAD = KS / 2;
    constexpr int TH = 8, TW = 16;
    constexpr int SH = TH + KS - 1, SW = TW + KS - 1;
    constexpr int CHUNK = (KS == 3) ? 8 : 4;
    constexpr int KS2 = KS * KS;
    __shared__ float xs[CHUNK][SH][SW];
    __shared__ float ws[64][CHUNK][KS2];
    int b = blockIdx.y;
    int tile = blockIdx.x;
    int bx0 = (tile & 7) * TW, by0 = (tile >> 3) * TH;
    int tid = threadIdx.x;
    int ocq = tid >> 5, lane = tid & 31, py = lane >> 2, pxq = lane & 3;
    float acc[8][4];
    #pragma unroll
    for (int o = 0; o < 8; o++)
        #pragma unroll
        for (int p = 0; p < 4; p++) acc[o][p] = 0.f;

    const float* inb = in + ((size_t)b << 20);
    for (int ic0 = 0; ic0 < 64; ic0 += CHUNK) {
        __syncthreads();
        for (int e = tid; e < CHUNK * SH * SW; e += 256) {
            int i = e / (SH * SW), rem = e - i * (SH * SW);
            int r = rem / SW, cc = rem - r * SW;
            int gy = by0 + r - PAD, gx = bx0 + cc - PAD;
            float v = 0.f;
            if ((unsigned)gy < 128u && (unsigned)gx < 128u)
                v = inb[((ic0 + i) << 14) + (gy << 7) + gx];
            xs[i][r][cc] = v;
        }
        for (int e = tid; e < 64 * CHUNK * KS2; e += 256) {
            int oc = e / (CHUNK * KS2), rem = e - oc * (CHUNK * KS2);
            int i = rem / KS2, t = rem - i * KS2;
            ws[oc][i][t] = w[(oc * 64 + ic0 + i) * KS2 + t];
        }
        __syncthreads();
        for (int i = 0; i < CHUNK; i++) {
            #pragma unroll
            for (int ky = 0; ky < KS; ky++) {
                float xv[4 + KS - 1];
                #pragma unroll
                for (int j = 0; j < 4 + KS - 1; j++) xv[j] = xs[i][py + ky][pxq * 4 + j];
                #pragma unroll
                for (int o = 0; o < 8; o++) {
                    float wv[KS];
                    #pragma unroll
                    for (int t = 0; t < KS; t++) wv[t] = ws[ocq * 8 + o][i][ky * KS + t];
                    #pragma unroll
                    for (int p = 0; p < 4; p++)
                        #pragma unroll
                        for (int t = 0; t < KS; t++) acc[o][p] += xv[p + t] * wv[t];
                }
            }
        }
    }
    const float rsq = rsqrtf(1.f + EPSF);
    int y = by0 + py;
    #pragma unroll
    for (int o = 0; o < 8; o++) {
        int c = ocq * 8 + o;
        float s = gg[c] * rsq, beta = bb[c];
        #pragma unroll
        for (int p = 0; p < 4; p++) {
            int x = bx0 + pxq * 4 + p;
            int idx = ((b * 64 + c) << 14) + (y << 7) + x;
            float v = leakyf(acc[o][p] * s + beta);
            if (MODE == 0) out[idx] = v;
            else if (MODE == 1) out[idx] = sigmoidf(v);
            else if (MODE == 2) out[idx] = v * aux1[idx];
            else if (MODE == 3) out[idx] = sigmoidf(v) * aux1[idx] * aux2[idx];
            else out[idx] = v + aux1[idx] + aux2[idx];
        }
    }
}

// ---------------- per-sample depthwise multi-dilation ---------------------
// out[b,c] = sum_{d=1..3} dwconv(f2[b,c], k[b,c], dil=d, pad=2d); batch 0 -> f2[0].
// Then scaled by (1+kse).
__global__ __launch_bounds__(256) void multidil_k(
    const float* __restrict__ f2, const float* __restrict__ kk_g,
    const float* __restrict__ kse1, float* __restrict__ out) {
    __shared__ float xs[28][28];
    __shared__ float kk[25];
    int b = blockIdx.z, c = blockIdx.y;
    int txt = blockIdx.x & 7, tyt = blockIdx.x >> 3;
    int bx0 = txt * 16, by0 = tyt * 16;
    int tid = threadIdx.x;
    if (tid < 25) kk[tid] = kk_g[(b * 64 + c) * 25 + tid];
    const float* src = f2 + ((size_t)(b * 64 + c) << 14);
    for (int e = tid; e < 784; e += 256) {
        int r = e / 28, cc = e - r * 28;
        int gy = by0 + r - 6, gx = bx0 + cc - 6;
        float v = 0.f;
        if ((unsigned)gy < 128u && (unsigned)gx < 128u) v = src[(gy << 7) + gx];
        xs[r][cc] = v;
    }
    __syncthreads();
    int py = tid >> 4, px = tid & 15;
    int idx = ((b * 64 + c) << 14) + ((by0 + py) << 7) + bx0 + px;
    float kv = kse1[idx];
    float res;
    if (b == 0) {
        res = xs[py + 6][px + 6];
    } else {
        float a = 0.f;
        #pragma unroll
        for (int d = 1; d <= 3; d++)
            #pragma unroll
            for (int ky = 0; ky < 5; ky++)
                #pragma unroll
                for (int kx = 0; kx < 5; kx++)
                    a += xs[py + 6 + d * (ky - 2)][px + 6 + d * (kx - 2)] * kk[ky * 5 + kx];
        res = a;
    }
    out[idx] = res * kv;
}

// ---------------- host orchestration --------------------------------------
extern "C" void kernel_launch(void* const* d_in, const int* in_sizes, int n_in,
                              void* d_out, int out_size) {
    const float* x1      = (const float*)d_in[0];
    const float* kk      = (const float*)d_in[1];
    const float* conv1_w = (const float*)d_in[2];
    const float* conv1_g = (const float*)d_in[3];
    const float* conv1_b = (const float*)d_in[4];
    const float* conv2_w = (const float*)d_in[5];
    const float* conv2_g = (const float*)d_in[6];
    const float* conv2_b = (const float*)d_in[7];
    const float* conv_w  = (const float*)d_in[8];
    const float* conv_bi = (const float*)d_in[9];
    const float* c0_w    = (const float*)d_in[10];
    const float* c0_g    = (const float*)d_in[11];
    const float* c0_b    = (const float*)d_in[12];
    const float* attc_w  = (const float*)d_in[13];
    const float* attc_g  = (const float*)d_in[14];
    const float* attc_b  = (const float*)d_in[15];
    const float* c05_w   = (const float*)d_in[16];
    const float* c05_g   = (const float*)d_in[17];
    const float* c05_b   = (const float*)d_in[18];
    const float* c0a_w   = (const float*)d_in[19];
    const float* c0a_g   = (const float*)d_in[20];
    const float* c0a_b   = (const float*)d_in[21];
    const float* c0b_w   = (const float*)d_in[22];
    const float* c0b_g   = (const float*)d_in[23];
    const float* c0b_b   = (const float*)d_in[24];
    const float* se_w1   = (const float*)d_in[25];
    const float* se_w2   = (const float*)d_in[26];
    float* outp = (float*)d_out;

    float *kse1, *fuse, *f1, *f2, *eadd, *A1, *out1, *out2, *o2c, *fo2, *eo2, *o2f, *t1, *t2;
    float *va, *fb, *am, *ses;
    cudaGetSymbolAddress((void**)&kse1, g_kse1);
    cudaGetSymbolAddress((void**)&fuse, g_fuse);
    cudaGetSymbolAddress((void**)&f1,   g_f1);
    cudaGetSymbolAddress((void**)&f2,   g_f2);
    cudaGetSymbolAddress((void**)&eadd, g_eadd);
    cudaGetSymbolAddress((void**)&A1,   g_A1);
    cudaGetSymbolAddress((void**)&out1, g_out1);
    cudaGetSymbolAddress((void**)&out2, g_out2);
    cudaGetSymbolAddress((void**)&o2c,  g_o2c);
    cudaGetSymbolAddress((void**)&fo2,  g_fo2);
    cudaGetSymbolAddress((void**)&eo2,  g_eo2);
    cudaGetSymbolAddress((void**)&o2f,  g_o2f);
    cudaGetSymbolAddress((void**)&t1,   g_t1);
    cudaGetSymbolAddress((void**)&t2,   g_t2);
    cudaGetSymbolAddress((void**)&va,   g_va);
    cudaGetSymbolAddress((void**)&fb,   g_fb);
    cudaGetSymbolAddress((void**)&am,   g_am);
    cudaGetSymbolAddress((void**)&ses,  g_ses);

    dim3 blk(256);
    // 1. channel means of x1
    rowmean_k<<<1024, blk>>>(x1, va);
    // 2. fusebase
    fusebase_k<<<1, 512>>>(va, conv_w, conv_bi, fb);
    // 3. (1+kse)
    kse_k<<<NBIG / 256, blk>>>(kk, kse1);
    // 4. three 1x1 convs fused: fuseadd (scaled), f1, f2
    g1x1_triple_k<<<dim3(256, 3, 8), blk>>>(x1, conv_w, conv1_w, conv1_g, conv1_b,
                                            conv2_w, conv2_g, conv2_b, fb, kse1,
                                            fuse, f1, f2);
    // 5-6. SE scale from sigmoid(fuseadd)
    attmean_k<<<512, blk>>>(fuse, am);
    se_k<<<1, 512>>>(am, se_w1, se_w2, ses);
    // 7. eadd = bnlrelu(conv3(fuseadd, c0))
    conv_k<3, 0><<<dim3(128, 8), blk>>>(fuse, c0_w, c0_g, c0_b, nullptr, nullptr, eadd);
    // 8. A1 = sigmoid(bnlrelu(conv3(eadd, attc)))
    conv_k<3, 1><<<dim3(128, 8), blk>>>(eadd, attc_w, attc_g, attc_b, nullptr, nullptr, A1);
    // 9. out1 = bnlrelu(conv3(f1, c0)) * (1+kse)
    conv_k<3, 2><<<dim3(128, 8), blk>>>(f1, c0_w, c0_g, c0_b, kse1, nullptr, out1);
    // 10. out2 = multidil(f2, k) * (1+kse)
    multidil_k<<<dim3(64, 64, 8), blk>>>(f2, kk, kse1, out2);
    // 11. out2conv = bnlrelu(conv5(out2, c05))
    conv_k<5, 0><<<dim3(128, 8), blk>>>(out2, c05_w, c05_g, c05_b, nullptr, nullptr, o2c);
    // 12. fuseout2 = A1 * sigmoid(bnlrelu(conv3(out1, attc))) * out2conv
    conv_k<3, 3><<<dim3(128, 8), blk>>>(out1, attc_w, attc_g, attc_b, A1, o2c, fo2);
    // 13. eout2 = bnlrelu(conv5(fuseout2, c05)) + out2conv + f2
    conv_k<5, 4><<<dim3(128, 8), blk>>>(fo2, c05_w, c05_g, c05_b, o2c, f2, eo2);
    // 14. out2final = bnlrelu(conv5(eout2, c05))
    conv_k<5, 0><<<dim3(128, 8), blk>>>(eo2, c05_w, c05_g, c05_b, nullptr, nullptr, o2f);
    // 15. t1 = bnlrelu(conv0a(concat(out1, out2final)))
    g1x1_cat_k<<<dim3(256, 1, 8), blk>>>(out1, o2f, c0a_w, c0a_g, c0a_b, t1);
    // 16. t2 = bnlrelu(conv3(t1, conv0b))
    conv_k<3, 0><<<dim3(128, 8), blk>>>(t1, c0b_w, c0b_g, c0b_b, nullptr, nullptr, t2);
    // 17. out = sigmoid(fuse) * ses * t2 * A1
    final_k<<<NBIG / 256, blk>>>(fuse, ses, t2, A1, outp);
}

// round 5
// speedup vs baseline: 1.2474x; 1.2474x over previous
#include <cuda_runtime.h>
#include <math.h>

#define NBIG (8*64*128*128)
#define EPSF 1e-5f

// ---------------- scratch buffers (device globals; no allocation) ----------
__device__ float g_kse1[NBIG];
__device__ float g_fuse[NBIG];
__device__ float g_f1[NBIG];
__device__ float g_f2[NBIG];
__device__ float g_eadd[NBIG];
__device__ float g_A1[NBIG];
__device__ float g_out1[NBIG];
__device__ float g_out2[NBIG];
__device__ float g_o2c[NBIG];
__device__ float g_fo2[NBIG];
__device__ float g_eo2[NBIG];
__device__ float g_o2f[NBIG];
__device__ float g_t1[NBIG];
__device__ float g_t2[NBIG];
__device__ float g_va[1024];
__device__ float g_fb[512];
__device__ float g_am[512];
__device__ float g_ses[512];

__device__ __forceinline__ float leakyf(float x) { return x >= 0.f ? x : 0.01f * x; }
__device__ __forceinline__ float sigmoidf(float x) { return 1.f / (1.f + expf(-x)); }

// ---- packed f32x2 helpers (FFMA2 — ptxas never emits this from C++) ------
__device__ __forceinline__ unsigned long long pack2(float x) {
    unsigned long long r;
    asm("mov.b64 %0, {%1, %1};" : "=l"(r) : "f"(x));
    return r;
}
__device__ __forceinline__ void fma2(unsigned long long& acc, unsigned long long a, unsigned long long b) {
    asm("fma.rn.f32x2 %0, %1, %2, %0;" : "+l"(acc) : "l"(a), "l"(b));
}
__device__ __forceinline__ void unpack2(unsigned long long v, float& lo, float& hi) {
    asm("mov.b64 {%0, %1}, %2;" : "=f"(lo), "=f"(hi) : "l"(v));
}

__device__ __forceinline__ float blockReduceSum(float v) {
    __shared__ float sh[32];
    int lane = threadIdx.x & 31, wid = threadIdx.x >> 5;
    #pragma unroll
    for (int o = 16; o; o >>= 1) v += __shfl_down_sync(0xffffffffu, v, o);
    if (lane == 0) sh[wid] = v;
    __syncthreads();
    v = (threadIdx.x < (blockDim.x >> 5)) ? sh[lane] : 0.f;
    if (wid == 0) {
        #pragma unroll
        for (int o = 16; o; o >>= 1) v += __shfl_down_sync(0xffffffffu, v, o);
    }
    return v;
}

// ---------------- small kernels -------------------------------------------
__global__ __launch_bounds__(256) void rowmean_k(const float* __restrict__ x, float* __restrict__ out) {
    int row = blockIdx.x;
    const float* p = x + ((size_t)row << 14);
    float s = 0.f;
    for (int i = threadIdx.x; i < 16384; i += 256) s += p[i];
    s = blockReduceSum(s);
    if (threadIdx.x == 0) out[row] = s * (1.f / 16384.f);
}

__global__ __launch_bounds__(256) void attmean_k(const float* __restrict__ x, float* __restrict__ out) {
    int row = blockIdx.x;
    const float* p = x + ((size_t)row << 14);
    float s = 0.f;
    for (int i = threadIdx.x; i < 16384; i += 256) s += sigmoidf(p[i]);
    s = blockReduceSum(s);
    if (threadIdx.x == 0) out[row] = s * (1.f / 16384.f);
}

__global__ void fusebase_k(const float* __restrict__ va, const float* __restrict__ cw,
                           const float* __restrict__ bias, float* __restrict__ fb) {
    int t = threadIdx.x;  // 512
    int b = t >> 6, c = t & 63;
    float s = 0.f;
    for (int i = 0; i < 128; i++) s += cw[c * 128 + i] * va[b * 128 + i];
    fb[t] = s + 2.f * bias[c];
}

__global__ void se_k(const float* __restrict__ am, const float* __restrict__ w1,
                     const float* __restrict__ w2, float* __restrict__ ses) {
    __shared__ float z[8][4];
    int t = threadIdx.x;  // 512
    if (t < 32) {
        int b = t >> 2, j = t & 3;
        float s = 0.f;
        for (int c = 0; c < 64; c++) s += w1[j * 64 + c] * am[b * 64 + c];
        z[b][j] = leakyf(s);
    }
    __syncthreads();
    int b = t >> 6, c = t & 63;
    float s = 0.f;
    #pragma unroll
    for (int j = 0; j < 4; j++) s += z[b][j] * w2[c * 4 + j];
    ses[t] = sigmoidf(s);
}

__global__ __launch_bounds__(256) void kse_k(const float* __restrict__ k, float* __restrict__ out) {
    int idx = blockIdx.x * 256 + threadIdx.x;
    int w = idx & 127, h = (idx >> 7) & 127, bc = idx >> 14;
    const float st = 4.0f / 127.0f;
    float ys = h * st, xs = w * st;
    int y0 = (int)floorf(ys); if (y0 > 4) y0 = 4; if (y0 < 0) y0 = 0;
    int x0 = (int)floorf(xs); if (x0 > 4) x0 = 4; if (x0 < 0) x0 = 0;
    int y1 = min(y0 + 1, 4), x1 = min(x0 + 1, 4);
    float wy = ys - (float)y0, wx = xs - (float)x0;
    const float* kb = k + bc * 25;
    float r0 = kb[y0 * 5 + x0] * (1.f - wx) + kb[y0 * 5 + x1] * wx;
    float r1 = kb[y1 * 5 + x0] * (1.f - wx) + kb[y1 * 5 + x1] * wx;
    out[idx] = 1.f + (r0 * (1.f - wy) + r1 * wy);
}

__global__ __launch_bounds__(256) void final_k(const float* __restrict__ fuse, const float* __restrict__ ses,
                                               const float* __restrict__ t2, const float* __restrict__ A1,
                                               float* __restrict__ out) {
    int idx = blockIdx.x * 256 + threadIdx.x;
    int bc = idx >> 14;
    out[idx] = sigmoidf(fuse[idx]) * ses[bc] * t2[idx] * A1[idx];
}

// ---------------- 1x1 convs as SGEMM (f32x2 inner product) -----------------
__global__ __launch_bounds__(256) void g1x1_triple_k(
    const float* __restrict__ x1,
    const float* __restrict__ wf, const float* __restrict__ w1c,
    const float* __restrict__ g1, const float* __restrict__ b1,
    const float* __restrict__ w2c, const float* __restrict__ g2, const float* __restrict__ b2,
    const float* __restrict__ fb, const float* __restrict__ kse1,
    float* __restrict__ ofuse, float* __restrict__ of1, float* __restrict__ of2) {
    __shared__ __align__(16) float As[16][68];
    __shared__ __align__(16) float Bs[16][64];
    int convid = blockIdx.y, b = blockIdx.z, n0 = blockIdx.x * 64;
    const float* W = convid == 0 ? wf : (convid == 1 ? w1c : w2c);
    int tid = threadIdx.x, ty = tid >> 4, tx = tid & 15;
    unsigned long long acc2[4][2] = {};
    for (int k0 = 0; k0 < 128; k0 += 16) {
        __syncthreads();
        {
            int m = tid >> 2, kq = (tid & 3) * 4;
            float4 a4 = *reinterpret_cast<const float4*>(W + m * 128 + k0 + kq);
            As[kq + 0][m] = a4.x; As[kq + 1][m] = a4.y; As[kq + 2][m] = a4.z; As[kq + 3][m] = a4.w;
        }
        #pragma unroll
        for (int l = 0; l < 4; l++) {
            int e = tid + l * 256, kk = e >> 6, n = e & 63;
            Bs[kk][n] = x1[((b * 128 + k0 + kk) << 14) + n0 + n];
        }
        __syncthreads();
        #pragma unroll
        for (int kk = 0; kk < 16; kk++) {
            float4 a = *reinterpret_cast<const float4*>(&As[kk][ty * 4]);
            unsigned long long b01 = *reinterpret_cast<const unsigned long long*>(&Bs[kk][tx * 4]);
            unsigned long long b23 = *reinterpret_cast<const unsigned long long*>(&Bs[kk][tx * 4 + 2]);
            unsigned long long aa0 = pack2(a.x), aa1 = pack2(a.y), aa2 = pack2(a.z), aa3 = pack2(a.w);
            fma2(acc2[0][0], aa0, b01); fma2(acc2[0][1], aa0, b23);
            fma2(acc2[1][0], aa1, b01); fma2(acc2[1][1], aa1, b23);
            fma2(acc2[2][0], aa2, b01); fma2(acc2[2][1], aa2, b23);
            fma2(acc2[3][0], aa3, b01); fma2(acc2[3][1], aa3, b23);
        }
    }
    const float rs = rsqrtf(1.f + EPSF);
    #pragma unroll
    for (int i = 0; i < 4; i++) {
        int c = ty * 4 + i;
        #pragma unroll
        for (int j2 = 0; j2 < 2; j2++) {
            float v0, v1;
            unpack2(acc2[i][j2], v0, v1);
            float vv[2] = {v0, v1};
            #pragma unroll
            for (int u = 0; u < 2; u++) {
                int idx = ((b * 64 + c) << 14) + n0 + tx * 4 + j2 * 2 + u;
                if (convid == 0) {
                    float v = vv[u] + fb[b * 64 + c];
                    ofuse[idx] = v * kse1[idx];
                } else if (convid == 1) {
                    of1[idx] = leakyf(vv[u] * (g1[c] * rs) + b1[c]);
                } else {
                    of2[idx] = leakyf(vv[u] * (g2[c] * rs) + b2[c]);
                }
            }
        }
    }
}

__global__ __launch_bounds__(256) void g1x1_cat_k(
    const float* __restrict__ p1, const float* __restrict__ p2,
    const float* __restrict__ W, const float* __restrict__ gg, const float* __restrict__ bb,
    float* __restrict__ out) {
    __shared__ __align__(16) float As[16][68];
    __shared__ __align__(16) float Bs[16][64];
    int b = blockIdx.z, n0 = blockIdx.x * 64;
    int tid = threadIdx.x, ty = tid >> 4, tx = tid & 15;
    unsigned long long acc2[4][2] = {};
    for (int k0 = 0; k0 < 128; k0 += 16) {
        __syncthreads();
        {
            int m = tid >> 2, kq = (tid & 3) * 4;
            float4 a4 = *reinterpret_cast<const float4*>(W + m * 128 + k0 + kq);
            As[kq + 0][m] = a4.x; As[kq + 1][m] = a4.y; As[kq + 2][m] = a4.z; As[kq + 3][m] = a4.w;
        }
        #pragma unroll
        for (int l = 0; l < 4; l++) {
            int e = tid + l * 256, kk = e >> 6, n = e & 63;
            int ic = k0 + kk;
            const float* src = (ic < 64) ? (p1 + ((b * 64 + ic) << 14))
                                         : (p2 + ((b * 64 + ic - 64) << 14));
            Bs[kk][n] = src[n0 + n];
        }
        __syncthreads();
        #pragma unroll
        for (int kk = 0; kk < 16; kk++) {
            float4 a = *reinterpret_cast<const float4*>(&As[kk][ty * 4]);
            unsigned long long b01 = *reinterpret_cast<const unsigned long long*>(&Bs[kk][tx * 4]);
            unsigned long long b23 = *reinterpret_cast<const unsigned long long*>(&Bs[kk][tx * 4 + 2]);
            unsigned long long aa0 = pack2(a.x), aa1 = pack2(a.y), aa2 = pack2(a.z), aa3 = pack2(a.w);
            fma2(acc2[0][0], aa0, b01); fma2(acc2[0][1], aa0, b23);
            fma2(acc2[1][0], aa1, b01); fma2(acc2[1][1], aa1, b23);
            fma2(acc2[2][0], aa2, b01); fma2(acc2[2][1], aa2, b23);
            fma2(acc2[3][0], aa3, b01); fma2(acc2[3][1], aa3, b23);
        }
    }
    const float rs = rsqrtf(1.f + EPSF);
    #pragma unroll
    for (int i = 0; i < 4; i++) {
        int c = ty * 4 + i;
        float s = gg[c] * rs, beta = bb[c];
        #pragma unroll
        for (int j2 = 0; j2 < 2; j2++) {
            float v0, v1;
            unpack2(acc2[i][j2], v0, v1);
            int idx = ((b * 64 + c) << 14) + n0 + tx * 4 + j2 * 2;
            out[idx]     = leakyf(v0 * s + beta);
            out[idx + 1] = leakyf(v1 * s + beta);
        }
    }
}

// ---------------- direct conv (64->64), f32x2 over oc-pairs ---------------
// MODE 0: bnlrelu | 1: sigmoid(bnlrelu) | 2: *aux1 | 3: sigmoid()*aux1*aux2 | 4: +aux1+aux2
template <int KS, int MODE>
__global__ __launch_bounds__(256) void conv_k(
    const float* __restrict__ in, const float* __restrict__ w,
    const float* __restrict__ gg, const float* __restrict__ bb,
    const float* __restrict__ aux1, const float* __restrict__ aux2,
    float* __restrict__ out) {
    constexpr int PAD = KS / 2;
    constexpr int TH = 8, TW = 16;
    constexpr int SH = TH + KS - 1, SW = TW + KS - 1;
    constexpr int CHUNK = (KS == 3) ? 8 : 4;
    constexpr int KS2 = KS * KS;
    constexpr int OCP = 66;  // padded oc dim: even stride, 8B-aligned pairs, conflict-light
    __shared__ float xs[CHUNK][SH][SW];
    __shared__ __align__(16) float ws[CHUNK][KS2][OCP];
    int b = blockIdx.y;
    int tile = blockIdx.x;
    int bx0 = (tile & 7) * TW, by0 = (tile >> 3) * TH;
    int tid = threadIdx.x;
    int ocq = tid >> 5, lane = tid & 31, py = lane >> 2, pxq = lane & 3;
    unsigned long long acc2[4][4] = {};  // [oc-pair][pixel] packed (oc_even, oc_odd)

    const float* inb = in + ((size_t)b << 20);
    for (int ic0 = 0; ic0 < 64; ic0 += CHUNK) {
        __syncthreads();
        for (int e = tid; e < CHUNK * SH * SW; e += 256) {
            int i = e / (SH * SW), rem = e - i * (SH * SW);
            int r = rem / SW, cc = rem - r * SW;
            int gy = by0 + r - PAD, gx = bx0 + cc - PAD;
            float v = 0.f;
            if ((unsigned)gy < 128u && (unsigned)gx < 128u)
                v = inb[((ic0 + i) << 14) + (gy << 7) + gx];
            xs[i][r][cc] = v;
        }
        // stage weights transposed: ws[i][tap][oc] (oc contiguous -> LDS.64 pairs)
        for (int e = tid; e < 64 * CHUNK * KS2; e += 256) {
            int oc = e / (CHUNK * KS2), rem = e - oc * (CHUNK * KS2);
            int i = rem / KS2, t = rem - i * KS2;
            ws[i][t][oc] = w[(oc * 64 + ic0 + i) * KS2 + t];
        }
        __syncthreads();
        for (int i = 0; i < CHUNK; i++) {
            #pragma unroll
            for (int ky = 0; ky < KS; ky++) {
                unsigned long long xx[4 + KS - 1];
                #pragma unroll
                for (int j = 0; j < 4 + KS - 1; j++)
                    xx[j] = pack2(xs[i][py + ky][pxq * 4 + j]);
                #pragma unroll
                for (int o2 = 0; o2 < 4; o2++) {
                    unsigned long long wv[KS];
                    #pragma unroll
                    for (int t = 0; t < KS; t++)
                        wv[t] = *reinterpret_cast<const unsigned long long*>(
                            &ws[i][ky * KS + t][ocq * 8 + o2 * 2]);
                    #pragma unroll
                    for (int p = 0; p < 4; p++)
                        #pragma unroll
                        for (int t = 0; t < KS; t++)
                            fma2(acc2[o2][p], xx[p + t], wv[t]);
                }
            }
        }
    }
    const float rsq = rsqrtf(1.f + EPSF);
    int y = by0 + py;
    #pragma unroll
    for (int o2 = 0; o2 < 4; o2++) {
        int c0 = ocq * 8 + o2 * 2;
        float s0 = gg[c0] * rsq,     beta0 = bb[c0];
        float s1 = gg[c0 + 1] * rsq, beta1 = bb[c0 + 1];
        #pragma unroll
        for (int p = 0; p < 4; p++) {
            float vlo, vhi;
            unpack2(acc2[o2][p], vlo, vhi);
            int x = bx0 + pxq * 4 + p;
            float rv[2] = {vlo * s0 + beta0, vhi * s1 + beta1};
            #pragma unroll
            for (int u = 0; u < 2; u++) {
                int c = c0 + u;
                int idx = ((b * 64 + c) << 14) + (y << 7) + x;
                float v = leakyf(rv[u]);
                if (MODE == 0) out[idx] = v;
                else if (MODE == 1) out[idx] = sigmoidf(v);
                else if (MODE == 2) out[idx] = v * aux1[idx];
                else if (MODE == 3) out[idx] = sigmoidf(v) * aux1[idx] * aux2[idx];
                else out[idx] = v + aux1[idx] + aux2[idx];
            }
        }
    }
}

// ---------------- per-sample depthwise multi-dilation ---------------------
__global__ __launch_bounds__(256) void multidil_k(
    const float* __restrict__ f2, const float* __restrict__ kk_g,
    const float* __restrict__ kse1, float* __restrict__ out) {
    __shared__ float xs[28][28];
    __shared__ float kk[25];
    int b = blockIdx.z, c = blockIdx.y;
    int txt = blockIdx.x & 7, tyt = blockIdx.x >> 3;
    int bx0 = txt * 16, by0 = tyt * 16;
    int tid = threadIdx.x;
    if (tid < 25) kk[tid] = kk_g[(b * 64 + c) * 25 + tid];
    const float* src = f2 + ((size_t)(b * 64 + c) << 14);
    for (int e = tid; e < 784; e += 256) {
        int r = e / 28, cc = e - r * 28;
        int gy = by0 + r - 6, gx = bx0 + cc - 6;
        float v = 0.f;
        if ((unsigned)gy < 128u && (unsigned)gx < 128u) v = src[(gy << 7) + gx];
        xs[r][cc] = v;
    }
    __syncthreads();
    int py = tid >> 4, px = tid & 15;
    int idx = ((b * 64 + c) << 14) + ((by0 + py) << 7) + bx0 + px;
    float kv = kse1[idx];
    float res;
    if (b == 0) {
        res = xs[py + 6][px + 6];
    } else {
        float a = 0.f;
        #pragma unroll
        for (int d = 1; d <= 3; d++)
            #pragma unroll
            for (int ky = 0; ky < 5; ky++)
                #pragma unroll
                for (int kx = 0; kx < 5; kx++)
                    a += xs[py + 6 + d * (ky - 2)][px + 6 + d * (kx - 2)] * kk[ky * 5 + kx];
        res = a;
    }
    out[idx] = res * kv;
}

// ---------------- host orchestration --------------------------------------
extern "C" void kernel_launch(void* const* d_in, const int* in_sizes, int n_in,
                              void* d_out, int out_size) {
    const float* x1      = (const float*)d_in[0];
    const float* kk      = (const float*)d_in[1];
    const float* conv1_w = (const float*)d_in[2];
    const float* conv1_g = (const float*)d_in[3];
    const float* conv1_b = (const float*)d_in[4];
    const float* conv2_w = (const float*)d_in[5];
    const float* conv2_g = (const float*)d_in[6];
    const float* conv2_b = (const float*)d_in[7];
    const float* conv_w  = (const float*)d_in[8];
    const float* conv_bi = (const float*)d_in[9];
    const float* c0_w    = (const float*)d_in[10];
    const float* c0_g    = (const float*)d_in[11];
    const float* c0_b    = (const float*)d_in[12];
    const float* attc_w  = (const float*)d_in[13];
    const float* attc_g  = (const float*)d_in[14];
    const float* attc_b  = (const float*)d_in[15];
    const float* c05_w   = (const float*)d_in[16];
    const float* c05_g   = (const float*)d_in[17];
    const float* c05_b   = (const float*)d_in[18];
    const float* c0a_w   = (const float*)d_in[19];
    const float* c0a_g   = (const float*)d_in[20];
    const float* c0a_b   = (const float*)d_in[21];
    const float* c0b_w   = (const float*)d_in[22];
    const float* c0b_g   = (const float*)d_in[23];
    const float* c0b_b   = (const float*)d_in[24];
    const float* se_w1   = (const float*)d_in[25];
    const float* se_w2   = (const float*)d_in[26];
    float* outp = (float*)d_out;

    float *kse1, *fuse, *f1, *f2, *eadd, *A1, *out1, *out2, *o2c, *fo2, *eo2, *o2f, *t1, *t2;
    float *va, *fb, *am, *ses;
    cudaGetSymbolAddress((void**)&kse1, g_kse1);
    cudaGetSymbolAddress((void**)&fuse, g_fuse);
    cudaGetSymbolAddress((void**)&f1,   g_f1);
    cudaGetSymbolAddress((void**)&f2,   g_f2);
    cudaGetSymbolAddress((void**)&eadd, g_eadd);
    cudaGetSymbolAddress((void**)&A1,   g_A1);
    cudaGetSymbolAddress((void**)&out1, g_out1);
    cudaGetSymbolAddress((void**)&out2, g_out2);
    cudaGetSymbolAddress((void**)&o2c,  g_o2c);
    cudaGetSymbolAddress((void**)&fo2,  g_fo2);
    cudaGetSymbolAddress((void**)&eo2,  g_eo2);
    cudaGetSymbolAddress((void**)&o2f,  g_o2f);
    cudaGetSymbolAddress((void**)&t1,   g_t1);
    cudaGetSymbolAddress((void**)&t2,   g_t2);
    cudaGetSymbolAddress((void**)&va,   g_va);
    cudaGetSymbolAddress((void**)&fb,   g_fb);
    cudaGetSymbolAddress((void**)&am,   g_am);
    cudaGetSymbolAddress((void**)&ses,  g_ses);

    dim3 blk(256);
    rowmean_k<<<1024, blk>>>(x1, va);
    fusebase_k<<<1, 512>>>(va, conv_w, conv_bi, fb);
    kse_k<<<NBIG / 256, blk>>>(kk, kse1);
    g1x1_triple_k<<<dim3(256, 3, 8), blk>>>(x1, conv_w, conv1_w, conv1_g, conv1_b,
                                            conv2_w, conv2_g, conv2_b, fb, kse1,
                                            fuse, f1, f2);
    attmean_k<<<512, blk>>>(fuse, am);
    se_k<<<1, 512>>>(am, se_w1, se_w2, ses);
    conv_k<3, 0><<<dim3(128, 8), blk>>>(fuse, c0_w, c0_g, c0_b, nullptr, nullptr, eadd);
    conv_k<3, 1><<<dim3(128, 8), blk>>>(eadd, attc_w, attc_g, attc_b, nullptr, nullptr, A1);
    conv_k<3, 2><<<dim3(128, 8), blk>>>(f1, c0_w, c0_g, c0_b, kse1, nullptr, out1);
    multidil_k<<<dim3(64, 64, 8), blk>>>(f2, kk, kse1, out2);
    conv_k<5, 0><<<dim3(128, 8), blk>>>(out2, c05_w, c05_g, c05_b, nullptr, nullptr, o2c);
    conv_k<3, 3><<<dim3(128, 8), blk>>>(out1, attc_w, attc_g, attc_b, A1, o2c, fo2);
    conv_k<5, 4><<<dim3(128, 8), blk>>>(fo2, c05_w, c05_g, c05_b, o2c, f2, eo2);
    conv_k<5, 0><<<dim3(128, 8), blk>>>(eo2, c05_w, c05_g, c05_b, nullptr, nullptr, o2f);
    g1x1_cat_k<<<dim3(256, 1, 8), blk>>>(out1, o2f, c0a_w, c0a_g, c0a_b, t1);
    conv_k<3, 0><<<dim3(128, 8), blk>>>(t1, c0b_w, c0b_g, c0b_b, nullptr, nullptr, t2);
    final_k<<<NBIG / 256, blk>>>(fuse, ses, t2, A1, outp);
}

// round 6
// speedup vs baseline: 1.8701x; 1.4993x over previous
#include <cuda_runtime.h>
#include <math.h>
#include <stdint.h>

#define NBIG (8*64*128*128)
#define EPSF 1e-5f

// ---------------- scratch buffers (device globals; no allocation) ----------
__device__ float g_kse1[NBIG];
__device__ float g_fuse[NBIG];
__device__ float g_f1[NBIG];
__device__ float g_f2[NBIG];
__device__ float g_eadd[NBIG];
__device__ float g_A1[NBIG];
__device__ float g_out1[NBIG];
__device__ float g_out2[NBIG];
__device__ float g_o2c[NBIG];
__device__ float g_fo2[NBIG];
__device__ float g_eo2[NBIG];
__device__ float g_o2f[NBIG];
__device__ float g_t1[NBIG];
__device__ float g_t2[NBIG];
__device__ float g_va[1024];
__device__ float g_fb[512];
__device__ float g_am[512];
__device__ float g_ses[512];
// tf32-transposed conv weights: Wt[tap][ic][oc]
__device__ uint32_t g_wt_c0[64*64*9];
__device__ uint32_t g_wt_attc[64*64*9];
__device__ uint32_t g_wt_c0b[64*64*9];
__device__ uint32_t g_wt_c05[64*64*25];

__device__ __forceinline__ float leakyf(float x) { return x >= 0.f ? x : 0.01f * x; }
__device__ __forceinline__ float sigmoidf(float x) { return 1.f / (1.f + expf(-x)); }

__device__ __forceinline__ uint32_t to_tf32(float x) {
    uint32_t u;
    asm("cvt.rna.tf32.f32 %0, %1;" : "=r"(u) : "f"(x));
    return u;
}

#define MMA_TF32(d, a0, a1, a2, a3, b0, b1) \
    asm("mma.sync.aligned.m16n8k8.row.col.f32.tf32.tf32.f32 " \
        "{%0,%1,%2,%3}, {%4,%5,%6,%7}, {%8,%9}, {%0,%1,%2,%3};" \
        : "+f"(d[0]), "+f"(d[1]), "+f"(d[2]), "+f"(d[3]) \
        : "r"(a0), "r"(a1), "r"(a2), "r"(a3), "r"(b0), "r"(b1))

// ---- packed f32x2 helpers (kept for the 1x1 GEMMs) -----------------------
__device__ __forceinline__ unsigned long long pack2(float x) {
    unsigned long long r;
    asm("mov.b64 %0, {%1, %1};" : "=l"(r) : "f"(x));
    return r;
}
__device__ __forceinline__ void fma2(unsigned long long& acc, unsigned long long a, unsigned long long b) {
    asm("fma.rn.f32x2 %0, %1, %2, %0;" : "+l"(acc) : "l"(a), "l"(b));
}
__device__ __forceinline__ void unpack2(unsigned long long v, float& lo, float& hi) {
    asm("mov.b64 {%0, %1}, %2;" : "=f"(lo), "=f"(hi) : "l"(v));
}

__device__ __forceinline__ float blockReduceSum(float v) {
    __shared__ float sh[32];
    int lane = threadIdx.x & 31, wid = threadIdx.x >> 5;
    #pragma unroll
    for (int o = 16; o; o >>= 1) v += __shfl_down_sync(0xffffffffu, v, o);
    if (lane == 0) sh[wid] = v;
    __syncthreads();
    v = (threadIdx.x < (blockDim.x >> 5)) ? sh[lane] : 0.f;
    if (wid == 0) {
        #pragma unroll
        for (int o = 16; o; o >>= 1) v += __shfl_down_sync(0xffffffffu, v, o);
    }
    return v;
}

// ---------------- small kernels -------------------------------------------
__global__ __launch_bounds__(256) void rowmean_k(const float* __restrict__ x, float* __restrict__ out) {
    int row = blockIdx.x;
    const float* p = x + ((size_t)row << 14);
    float s = 0.f;
    for (int i = threadIdx.x; i < 16384; i += 256) s += p[i];
    s = blockReduceSum(s);
    if (threadIdx.x == 0) out[row] = s * (1.f / 16384.f);
}

__global__ __launch_bounds__(256) void attmean_k(const float* __restrict__ x, float* __restrict__ out) {
    int row = blockIdx.x;
    const float* p = x + ((size_t)row << 14);
    float s = 0.f;
    for (int i = threadIdx.x; i < 16384; i += 256) s += sigmoidf(p[i]);
    s = blockReduceSum(s);
    if (threadIdx.x == 0) out[row] = s * (1.f / 16384.f);
}

__global__ void fusebase_k(const float* __restrict__ va, const float* __restrict__ cw,
                           const float* __restrict__ bias, float* __restrict__ fb) {
    int t = threadIdx.x;  // 512
    int b = t >> 6, c = t & 63;
    float s = 0.f;
    for (int i = 0; i < 128; i++) s += cw[c * 128 + i] * va[b * 128 + i];
    fb[t] = s + 2.f * bias[c];
}

__global__ void se_k(const float* __restrict__ am, const float* __restrict__ w1,
                     const float* __restrict__ w2, float* __restrict__ ses) {
    __shared__ float z[8][4];
    int t = threadIdx.x;  // 512
    if (t < 32) {
        int b = t >> 2, j = t & 3;
        float s = 0.f;
        for (int c = 0; c < 64; c++) s += w1[j * 64 + c] * am[b * 64 + c];
        z[b][j] = leakyf(s);
    }
    __syncthreads();
    int b = t >> 6, c = t & 63;
    float s = 0.f;
    #pragma unroll
    for (int j = 0; j < 4; j++) s += z[b][j] * w2[c * 4 + j];
    ses[t] = sigmoidf(s);
}

__global__ __launch_bounds__(256) void kse_k(const float* __restrict__ k, float* __restrict__ out) {
    int idx = blockIdx.x * 256 + threadIdx.x;
    int w = idx & 127, h = (idx >> 7) & 127, bc = idx >> 14;
    const float st = 4.0f / 127.0f;
    float ys = h * st, xs = w * st;
    int y0 = (int)floorf(ys); if (y0 > 4) y0 = 4; if (y0 < 0) y0 = 0;
    int x0 = (int)floorf(xs); if (x0 > 4) x0 = 4; if (x0 < 0) x0 = 0;
    int y1 = min(y0 + 1, 4), x1 = min(x0 + 1, 4);
    float wy = ys - (float)y0, wx = xs - (float)x0;
    const float* kb = k + bc * 25;
    float r0 = kb[y0 * 5 + x0] * (1.f - wx) + kb[y0 * 5 + x1] * wx;
    float r1 = kb[y1 * 5 + x0] * (1.f - wx) + kb[y1 * 5 + x1] * wx;
    out[idx] = 1.f + (r0 * (1.f - wy) + r1 * wy);
}

__global__ __launch_bounds__(256) void final_k(const float* __restrict__ fuse, const float* __restrict__ ses,
                                               const float* __restrict__ t2, const float* __restrict__ A1,
                                               float* __restrict__ out) {
    int idx = blockIdx.x * 256 + threadIdx.x;
    int bc = idx >> 14;
    out[idx] = sigmoidf(fuse[idx]) * ses[bc] * t2[idx] * A1[idx];
}

// weight transpose+tf32 prep: wt[(tap*64+ic)*64+oc] = tf32(w[(oc*64+ic)*KS2+tap])
__global__ void wprep_k(const float* __restrict__ w, uint32_t* __restrict__ wt, int KS2, int n) {
    int idx = blockIdx.x * 256 + threadIdx.x;
    if (idx >= n) return;
    int oc = idx & 63, t2 = idx >> 6;
    int ic = t2 & 63, tap = t2 >> 6;
    wt[idx] = to_tf32(w[(oc * 64 + ic) * KS2 + tap]);
}

// ---------------- 1x1 convs as SGEMM (f32x2 inner product) -----------------
__global__ __launch_bounds__(256) void g1x1_triple_k(
    const float* __restrict__ x1,
    const float* __restrict__ wf, const float* __restrict__ w1c,
    const float* __restrict__ g1, const float* __restrict__ b1,
    const float* __restrict__ w2c, const float* __restrict__ g2, const float* __restrict__ b2,
    const float* __restrict__ fb, const float* __restrict__ kse1,
    float* __restrict__ ofuse, float* __restrict__ of1, float* __restrict__ of2) {
    __shared__ __align__(16) float As[16][68];
    __shared__ __align__(16) float Bs[16][64];
    int convid = blockIdx.y, b = blockIdx.z, n0 = blockIdx.x * 64;
    const float* W = convid == 0 ? wf : (convid == 1 ? w1c : w2c);
    int tid = threadIdx.x, ty = tid >> 4, tx = tid & 15;
    unsigned long long acc2[4][2] = {};
    for (int k0 = 0; k0 < 128; k0 += 16) {
        __syncthreads();
        {
            int m = tid >> 2, kq = (tid & 3) * 4;
            float4 a4 = *reinterpret_cast<const float4*>(W + m * 128 + k0 + kq);
            As[kq + 0][m] = a4.x; As[kq + 1][m] = a4.y; As[kq + 2][m] = a4.z; As[kq + 3][m] = a4.w;
        }
        #pragma unroll
        for (int l = 0; l < 4; l++) {
            int e = tid + l * 256, kk = e >> 6, n = e & 63;
            Bs[kk][n] = x1[((b * 128 + k0 + kk) << 14) + n0 + n];
        }
        __syncthreads();
        #pragma unroll
        for (int kk = 0; kk < 16; kk++) {
            float4 a = *reinterpret_cast<const float4*>(&As[kk][ty * 4]);
            unsigned long long b01 = *reinterpret_cast<const unsigned long long*>(&Bs[kk][tx * 4]);
            unsigned long long b23 = *reinterpret_cast<const unsigned long long*>(&Bs[kk][tx * 4 + 2]);
            unsigned long long aa0 = pack2(a.x), aa1 = pack2(a.y), aa2 = pack2(a.z), aa3 = pack2(a.w);
            fma2(acc2[0][0], aa0, b01); fma2(acc2[0][1], aa0, b23);
            fma2(acc2[1][0], aa1, b01); fma2(acc2[1][1], aa1, b23);
            fma2(acc2[2][0], aa2, b01); fma2(acc2[2][1], aa2, b23);
            fma2(acc2[3][0], aa3, b01); fma2(acc2[3][1], aa3, b23);
        }
    }
    const float rs = rsqrtf(1.f + EPSF);
    #pragma unroll
    for (int i = 0; i < 4; i++) {
        int c = ty * 4 + i;
        #pragma unroll
        for (int j2 = 0; j2 < 2; j2++) {
            float v0, v1;
            unpack2(acc2[i][j2], v0, v1);
            float vv[2] = {v0, v1};
            #pragma unroll
            for (int u = 0; u < 2; u++) {
                int idx = ((b * 64 + c) << 14) + n0 + tx * 4 + j2 * 2 + u;
                if (convid == 0) {
                    float v = vv[u] + fb[b * 64 + c];
                    ofuse[idx] = v * kse1[idx];
                } else if (convid == 1) {
                    of1[idx] = leakyf(vv[u] * (g1[c] * rs) + b1[c]);
                } else {
                    of2[idx] = leakyf(vv[u] * (g2[c] * rs) + b2[c]);
                }
            }
        }
    }
}

__global__ __launch_bounds__(256) void g1x1_cat_k(
    const float* __restrict__ p1, const float* __restrict__ p2,
    const float* __restrict__ W, const float* __restrict__ gg, const float* __restrict__ bb,
    float* __restrict__ out) {
    __shared__ __align__(16) float As[16][68];
    __shared__ __align__(16) float Bs[16][64];
    int b = blockIdx.z, n0 = blockIdx.x * 64;
    int tid = threadIdx.x, ty = tid >> 4, tx = tid & 15;
    unsigned long long acc2[4][2] = {};
    for (int k0 = 0; k0 < 128; k0 += 16) {
        __syncthreads();
        {
            int m = tid >> 2, kq = (tid & 3) * 4;
            float4 a4 = *reinterpret_cast<const float4*>(W + m * 128 + k0 + kq);
            As[kq + 0][m] = a4.x; As[kq + 1][m] = a4.y; As[kq + 2][m] = a4.z; As[kq + 3][m] = a4.w;
        }
        #pragma unroll
        for (int l = 0; l < 4; l++) {
            int e = tid + l * 256, kk = e >> 6, n = e & 63;
            int ic = k0 + kk;
            const float* src = (ic < 64) ? (p1 + ((b * 64 + ic) << 14))
                                         : (p2 + ((b * 64 + ic - 64) << 14));
            Bs[kk][n] = src[n0 + n];
        }
        __syncthreads();
        #pragma unroll
        for (int kk = 0; kk < 16; kk++) {
            float4 a = *reinterpret_cast<const float4*>(&As[kk][ty * 4]);
            unsigned long long b01 = *reinterpret_cast<const unsigned long long*>(&Bs[kk][tx * 4]);
            unsigned long long b23 = *reinterpret_cast<const unsigned long long*>(&Bs[kk][tx * 4 + 2]);
            unsigned long long aa0 = pack2(a.x), aa1 = pack2(a.y), aa2 = pack2(a.z), aa3 = pack2(a.w);
            fma2(acc2[0][0], aa0, b01); fma2(acc2[0][1], aa0, b23);
            fma2(acc2[1][0], aa1, b01); fma2(acc2[1][1], aa1, b23);
            fma2(acc2[2][0], aa2, b01); fma2(acc2[2][1], aa2, b23);
            fma2(acc2[3][0], aa3, b01); fma2(acc2[3][1], aa3, b23);
        }
    }
    const float rs = rsqrtf(1.f + EPSF);
    #pragma unroll
    for (int i = 0; i < 4; i++) {
        int c = ty * 4 + i;
        float s = gg[c] * rs, beta = bb[c];
        #pragma unroll
        for (int j2 = 0; j2 < 2; j2++) {
            float v0, v1;
            unpack2(acc2[i][j2], v0, v1);
            int idx = ((b * 64 + c) << 14) + n0 + tx * 4 + j2 * 2;
            out[idx]     = leakyf(v0 * s + beta);
            out[idx + 1] = leakyf(v1 * s + beta);
        }
    }
}

// ---------------- direct conv via tf32 mma.sync (implicit GEMM) -----------
// M = 64 oc, N = pixels (16x16 patch per CTA), K = ic, taps accumulated.
// warp w: m-tile = (w&3)*16 oc, column half = (w>>2)*8 px, 16 rows -> 64 accs.
// MODE 0: bnlrelu | 1: sigmoid(bnlrelu) | 2: *aux1 | 3: sigmoid()*aux1*aux2 | 4: +aux1+aux2
template <int KS, int MODE>
__global__ __launch_bounds__(256) void conv_mma_k(
    const float* __restrict__ in, const uint32_t* __restrict__ wt,
    const float* __restrict__ gg, const float* __restrict__ bb,
    const float* __restrict__ aux1, const float* __restrict__ aux2,
    float* __restrict__ out) {
    constexpr int PAD = KS / 2;
    constexpr int SH = 16 + KS - 1, SW = 16 + KS - 1;
    constexpr int SWP = (KS == 3) ? 20 : 28;  // plane stride SH*SWP % 32 == 8 -> conflict-free B frags
    __shared__ uint32_t xs[8][SH][SWP];
    int b = blockIdx.y, tile = blockIdx.x;
    int bx0 = (tile & 7) * 16, by0 = (tile >> 3) * 16;
    int tid = threadIdx.x, wid = tid >> 5, lane = tid & 31;
    int gq = lane >> 2, tig = lane & 3;
    int oc0 = (wid & 3) * 16, xh = (wid >> 2) * 8;

    float acc[16][4];
    #pragma unroll
    for (int y = 0; y < 16; y++)
        #pragma unroll
        for (int j = 0; j < 4; j++) acc[y][j] = 0.f;

    const float* inb = in + ((size_t)b << 20);
    for (int ic0 = 0; ic0 < 64; ic0 += 8) {
        __syncthreads();
        for (int e = tid; e < 8 * SH * SW; e += 256) {
            int i = e / (SH * SW), rem = e - i * (SH * SW);
            int r = rem / SW, c = rem - r * SW;
            int gy = by0 + r - PAD, gx = bx0 + c - PAD;
            float v = 0.f;
            if ((unsigned)gy < 128u && (unsigned)gx < 128u)
                v = inb[((ic0 + i) << 14) + (gy << 7) + gx];
            xs[i][r][c] = to_tf32(v);
        }
        __syncthreads();
        #pragma unroll 1
        for (int ky = 0; ky < KS; ky++) {
            #pragma unroll
            for (int kx = 0; kx < KS; kx++) {
                int tap = ky * KS + kx;
                const uint32_t* wp = wt + (((tap << 6) + ic0) << 6);
                uint32_t a0 = wp[(tig << 6) + oc0 + gq];
                uint32_t a1 = wp[(tig << 6) + oc0 + 8 + gq];
                uint32_t a2 = wp[((tig + 4) << 6) + oc0 + gq];
                uint32_t a3 = wp[((tig + 4) << 6) + oc0 + 8 + gq];
                #pragma unroll
                for (int y = 0; y < 16; y++) {
                    uint32_t b0 = xs[tig][y + ky][xh + kx + gq];
                    uint32_t b1 = xs[tig + 4][y + ky][xh + kx + gq];
                    MMA_TF32(acc[y], a0, a1, a2, a3, b0, b1);
                }
            }
        }
    }

    const float rsq = rsqrtf(1.f + EPSF);
    int oc_lo = oc0 + gq, oc_hi = oc0 + 8 + gq;
    float s_lo = gg[oc_lo] * rsq, be_lo = bb[oc_lo];
    float s_hi = gg[oc_hi] * rsq, be_hi = bb[oc_hi];
    int x = bx0 + xh + tig * 2;
    size_t base_lo = ((size_t)(b * 64 + oc_lo) << 14);
    size_t base_hi = ((size_t)(b * 64 + oc_hi) << 14);
    #pragma unroll
    for (int y = 0; y < 16; y++) {
        int yp = by0 + y;
        float v[4] = { acc[y][0] * s_lo + be_lo, acc[y][1] * s_lo + be_lo,
                       acc[y][2] * s_hi + be_hi, acc[y][3] * s_hi + be_hi };
        size_t idx[4] = { base_lo + (yp << 7) + x, base_lo + (yp << 7) + x + 1,
                          base_hi + (yp << 7) + x, base_hi + (yp << 7) + x + 1 };
        #pragma unroll
        for (int j = 0; j < 4; j++) {
            float r = leakyf(v[j]);
            if (MODE == 0) out[idx[j]] = r;
            else if (MODE == 1) out[idx[j]] = sigmoidf(r);
            else if (MODE == 2) out[idx[j]] = r * aux1[idx[j]];
            else if (MODE == 3) out[idx[j]] = sigmoidf(r) * aux1[idx[j]] * aux2[idx[j]];
            else out[idx[j]] = r + aux1[idx[j]] + aux2[idx[j]];
        }
    }
}

// ---------------- per-sample depthwise multi-dilation ---------------------
__global__ __launch_bounds__(256) void multidil_k(
    const float* __restrict__ f2, const float* __restrict__ kk_g,
    const float* __restrict__ kse1, float* __restrict__ out) {
    __shared__ float xs[28][28];
    __shared__ float kk[25];
    int b = blockIdx.z, c = blockIdx.y;
    int txt = blockIdx.x & 7, tyt = blockIdx.x >> 3;
    int bx0 = txt * 16, by0 = tyt * 16;
    int tid = threadIdx.x;
    if (tid < 25) kk[tid] = kk_g[(b * 64 + c) * 25 + tid];
    const float* src = f2 + ((size_t)(b * 64 + c) << 14);
    for (int e = tid; e < 784; e += 256) {
        int r = e / 28, cc = e - r * 28;
        int gy = by0 + r - 6, gx = bx0 + cc - 6;
        float v = 0.f;
        if ((unsigned)gy < 128u && (unsigned)gx < 128u) v = src[(gy << 7) + gx];
        xs[r][cc] = v;
    }
    __syncthreads();
    int py = tid >> 4, px = tid & 15;
    int idx = ((b * 64 + c) << 14) + ((by0 + py) << 7) + bx0 + px;
    float kv = kse1[idx];
    float res;
    if (b == 0) {
        res = xs[py + 6][px + 6];
    } else {
        float a = 0.f;
        #pragma unroll
        for (int d = 1; d <= 3; d++)
            #pragma unroll
            for (int ky = 0; ky < 5; ky++)
                #pragma unroll
                for (int kx = 0; kx < 5; kx++)
                    a += xs[py + 6 + d * (ky - 2)][px + 6 + d * (kx - 2)] * kk[ky * 5 + kx];
        res = a;
    }
    out[idx] = res * kv;
}

// ---------------- host orchestration --------------------------------------
extern "C" void kernel_launch(void* const* d_in, const int* in_sizes, int n_in,
                              void* d_out, int out_size) {
    const float* x1      = (const float*)d_in[0];
    const float* kk      = (const float*)d_in[1];
    const float* conv1_w = (const float*)d_in[2];
    const float* conv1_g = (const float*)d_in[3];
    const float* conv1_b = (const float*)d_in[4];
    const float* conv2_w = (const float*)d_in[5];
    const float* conv2_g = (const float*)d_in[6];
    const float* conv2_b = (const float*)d_in[7];
    const float* conv_w  = (const float*)d_in[8];
    const float* conv_bi = (const float*)d_in[9];
    const float* c0_w    = (const float*)d_in[10];
    const float* c0_g    = (const float*)d_in[11];
    const float* c0_b    = (const float*)d_in[12];
    const float* attc_w  = (const float*)d_in[13];
    const float* attc_g  = (const float*)d_in[14];
    const float* attc_b  = (const float*)d_in[15];
    const float* c05_w   = (const float*)d_in[16];
    const float* c05_g   = (const float*)d_in[17];
    const float* c05_b   = (const float*)d_in[18];
    const float* c0a_w   = (const float*)d_in[19];
    const float* c0a_g   = (const float*)d_in[20];
    const float* c0a_b   = (const float*)d_in[21];
    const float* c0b_w   = (const float*)d_in[22];
    const float* c0b_g   = (const float*)d_in[23];
    const float* c0b_b   = (const float*)d_in[24];
    const float* se_w1   = (const float*)d_in[25];
    const float* se_w2   = (const float*)d_in[26];
    float* outp = (float*)d_out;

    float *kse1, *fuse, *f1, *f2, *eadd, *A1, *out1, *out2, *o2c, *fo2, *eo2, *o2f, *t1, *t2;
    float *va, *fb, *am, *ses;
    uint32_t *wt_c0, *wt_attc, *wt_c0b, *wt_c05;
    cudaGetSymbolAddress((void**)&kse1, g_kse1);
    cudaGetSymbolAddress((void**)&fuse, g_fuse);
    cudaGetSymbolAddress((void**)&f1,   g_f1);
    cudaGetSymbolAddress((void**)&f2,   g_f2);
    cudaGetSymbolAddress((void**)&eadd, g_eadd);
    cudaGetSymbolAddress((void**)&A1,   g_A1);
    cudaGetSymbolAddress((void**)&out1, g_out1);
    cudaGetSymbolAddress((void**)&out2, g_out2);
    cudaGetSymbolAddress((void**)&o2c,  g_o2c);
    cudaGetSymbolAddress((void**)&fo2,  g_fo2);
    cudaGetSymbolAddress((void**)&eo2,  g_eo2);
    cudaGetSymbolAddress((void**)&o2f,  g_o2f);
    cudaGetSymbolAddress((void**)&t1,   g_t1);
    cudaGetSymbolAddress((void**)&t2,   g_t2);
    cudaGetSymbolAddress((void**)&va,   g_va);
    cudaGetSymbolAddress((void**)&fb,   g_fb);
    cudaGetSymbolAddress((void**)&am,   g_am);
    cudaGetSymbolAddress((void**)&ses,  g_ses);
    cudaGetSymbolAddress((void**)&wt_c0,   g_wt_c0);
    cudaGetSymbolAddress((void**)&wt_attc, g_wt_attc);
    cudaGetSymbolAddress((void**)&wt_c0b,  g_wt_c0b);
    cudaGetSymbolAddress((void**)&wt_c05,  g_wt_c05);

    dim3 blk(256);
    dim3 cgrid(64, 8);
    // weight prep (tf32 transpose)
    wprep_k<<<(64*64*9 + 255) / 256, blk>>>(c0_w,   wt_c0,   9,  64*64*9);
    wprep_k<<<(64*64*9 + 255) / 256, blk>>>(attc_w, wt_attc, 9,  64*64*9);
    wprep_k<<<(64*64*9 + 255) / 256, blk>>>(c0b_w,  wt_c0b,  9,  64*64*9);
    wprep_k<<<(64*64*25 + 255) / 256, blk>>>(c05_w, wt_c05,  25, 64*64*25);

    rowmean_k<<<1024, blk>>>(x1, va);
    fusebase_k<<<1, 512>>>(va, conv_w, conv_bi, fb);
    kse_k<<<NBIG / 256, blk>>>(kk, kse1);
    g1x1_triple_k<<<dim3(256, 3, 8), blk>>>(x1, conv_w, conv1_w, conv1_g, conv1_b,
                                            conv2_w, conv2_g, conv2_b, fb, kse1,
                                            fuse, f1, f2);
    attmean_k<<<512, blk>>>(fuse, am);
    se_k<<<1, 512>>>(am, se_w1, se_w2, ses);
    conv_mma_k<3, 0><<<cgrid, blk>>>(fuse, wt_c0, c0_g, c0_b, nullptr, nullptr, eadd);
    conv_mma_k<3, 1><<<cgrid, blk>>>(eadd, wt_attc, attc_g, attc_b, nullptr, nullptr, A1);
    conv_mma_k<3, 2><<<cgrid, blk>>>(f1, wt_c0, c0_g, c0_b, kse1, nullptr, out1);
    multidil_k<<<dim3(64, 64, 8), blk>>>(f2, kk, kse1, out2);
    conv_mma_k<5, 0><<<cgrid, blk>>>(out2, wt_c05, c05_g, c05_b, nullptr, nullptr, o2c);
    conv_mma_k<3, 3><<<cgrid, blk>>>(out1, wt_attc, attc_g, attc_b, A1, o2c, fo2);
    conv_mma_k<5, 4><<<cgrid, blk>>>(fo2, wt_c05, c05_g, c05_b, o2c, f2, eo2);
    conv_mma_k<5, 0><<<cgrid, blk>>>(eo2, wt_c05, c05_g, c05_b, nullptr, nullptr, o2f);
    g1x1_cat_k<<<dim3(256, 1, 8), blk>>>(out1, o2f, c0a_w, c0a_g, c0a_b, t1);
    conv_mma_k<3, 0><<<cgrid, blk>>>(t1, wt_c0b, c0b_g, c0b_b, nullptr, nullptr, t2);
    final_k<<<NBIG / 256, blk>>>(fuse, ses, t2, A1, outp);
}

// round 8
// speedup vs baseline: 2.4393x; 1.3044x over previous
#include <cuda_runtime.h>
#include <math.h>
#include <stdint.h>

#define NBIG (8*64*128*128)
#define EPSF 1e-5f

// ---------------- scratch buffers (device globals; no allocation) ----------
__device__ float g_kse1[NBIG];
__device__ float g_fuse[NBIG];
__device__ float g_f1[NBIG];
__device__ float g_f2[NBIG];
__device__ float g_eadd[NBIG];
__device__ float g_A1[NBIG];
__device__ float g_out1[NBIG];
__device__ float g_out2[NBIG];
__device__ float g_o2c[NBIG];
__device__ float g_fo2[NBIG];
__device__ float g_eo2[NBIG];
__device__ float g_o2f[NBIG];
__device__ float g_t1[NBIG];
__device__ float g_t2[NBIG];
__device__ float g_va[1024];
__device__ float g_fb[512];
__device__ float g_am[512];
__device__ float g_ses[512];
// tf32-transposed conv weights: Wt[tap][ic][oc]
__device__ uint32_t g_wt_c0[64*64*9];
__device__ uint32_t g_wt_attc[64*64*9];
__device__ uint32_t g_wt_c0b[64*64*9];
__device__ uint32_t g_wt_c05[64*64*25];

__device__ __forceinline__ float leakyf(float x) { return x >= 0.f ? x : 0.01f * x; }
__device__ __forceinline__ float sigmoidf(float x) { return 1.f / (1.f + expf(-x)); }

__device__ __forceinline__ uint32_t to_tf32(float x) {
    uint32_t u;
    asm("cvt.rna.tf32.f32 %0, %1;" : "=r"(u) : "f"(x));
    return u;
}

#define MMA_TF32(d, a0, a1, a2, a3, b0, b1) \
    asm("mma.sync.aligned.m16n8k8.row.col.f32.tf32.tf32.f32 " \
        "{%0,%1,%2,%3}, {%4,%5,%6,%7}, {%8,%9}, {%0,%1,%2,%3};" \
        : "+f"(d[0]), "+f"(d[1]), "+f"(d[2]), "+f"(d[3]) \
        : "r"(a0), "r"(a1), "r"(a2), "r"(a3), "r"(b0), "r"(b1))

// ---- packed f32x2 helpers (kept for the 1x1 GEMMs) -----------------------
__device__ __forceinline__ unsigned long long pack2(float x) {
    unsigned long long r;
    asm("mov.b64 %0, {%1, %1};" : "=l"(r) : "f"(x));
    return r;
}
__device__ __forceinline__ void fma2(unsigned long long& acc, unsigned long long a, unsigned long long b) {
    asm("fma.rn.f32x2 %0, %1, %2, %0;" : "+l"(acc) : "l"(a), "l"(b));
}
__device__ __forceinline__ void unpack2(unsigned long long v, float& lo, float& hi) {
    asm("mov.b64 {%0, %1}, %2;" : "=f"(lo), "=f"(hi) : "l"(v));
}

__device__ __forceinline__ float blockReduceSum(float v) {
    __shared__ float sh[32];
    int lane = threadIdx.x & 31, wid = threadIdx.x >> 5;
    #pragma unroll
    for (int o = 16; o; o >>= 1) v += __shfl_down_sync(0xffffffffu, v, o);
    if (lane == 0) sh[wid] = v;
    __syncthreads();
    v = (threadIdx.x < (blockDim.x >> 5)) ? sh[lane] : 0.f;
    if (wid == 0) {
        #pragma unroll
        for (int o = 16; o; o >>= 1) v += __shfl_down_sync(0xffffffffu, v, o);
    }
    return v;
}

// ---------------- small kernels -------------------------------------------
__global__ __launch_bounds__(256) void rowmean_k(const float* __restrict__ x, float* __restrict__ out) {
    int row = blockIdx.x;
    const float* p = x + ((size_t)row << 14);
    float s = 0.f;
    for (int i = threadIdx.x; i < 16384; i += 256) s += p[i];
    s = blockReduceSum(s);
    if (threadIdx.x == 0) out[row] = s * (1.f / 16384.f);
}

__global__ __launch_bounds__(256) void attmean_k(const float* __restrict__ x, float* __restrict__ out) {
    int row = blockIdx.x;
    const float* p = x + ((size_t)row << 14);
    float s = 0.f;
    for (int i = threadIdx.x; i < 16384; i += 256) s += sigmoidf(p[i]);
    s = blockReduceSum(s);
    if (threadIdx.x == 0) out[row] = s * (1.f / 16384.f);
}

__global__ void fusebase_k(const float* __restrict__ va, const float* __restrict__ cw,
                           const float* __restrict__ bias, float* __restrict__ fb) {
    int t = threadIdx.x;  // 512
    int b = t >> 6, c = t & 63;
    float s = 0.f;
    for (int i = 0; i < 128; i++) s += cw[c * 128 + i] * va[b * 128 + i];
    fb[t] = s + 2.f * bias[c];
}

__global__ void se_k(const float* __restrict__ am, const float* __restrict__ w1,
                     const float* __restrict__ w2, float* __restrict__ ses) {
    __shared__ float z[8][4];
    int t = threadIdx.x;  // 512
    if (t < 32) {
        int b = t >> 2, j = t & 3;
        float s = 0.f;
        for (int c = 0; c < 64; c++) s += w1[j * 64 + c] * am[b * 64 + c];
        z[b][j] = leakyf(s);
    }
    __syncthreads();
    int b = t >> 6, c = t & 63;
    float s = 0.f;
    #pragma unroll
    for (int j = 0; j < 4; j++) s += z[b][j] * w2[c * 4 + j];
    ses[t] = sigmoidf(s);
}

__global__ __launch_bounds__(256) void kse_k(const float* __restrict__ k, float* __restrict__ out) {
    int idx = blockIdx.x * 256 + threadIdx.x;
    int w = idx & 127, h = (idx >> 7) & 127, bc = idx >> 14;
    const float st = 4.0f / 127.0f;
    float ys = h * st, xs = w * st;
    int y0 = (int)floorf(ys); if (y0 > 4) y0 = 4; if (y0 < 0) y0 = 0;
    int x0 = (int)floorf(xs); if (x0 > 4) x0 = 4; if (x0 < 0) x0 = 0;
    int y1 = min(y0 + 1, 4), x1 = min(x0 + 1, 4);
    float wy = ys - (float)y0, wx = xs - (float)x0;
    const float* kb = k + bc * 25;
    float r0 = kb[y0 * 5 + x0] * (1.f - wx) + kb[y0 * 5 + x1] * wx;
    float r1 = kb[y1 * 5 + x0] * (1.f - wx) + kb[y1 * 5 + x1] * wx;
    out[idx] = 1.f + (r0 * (1.f - wy) + r1 * wy);
}

__global__ __launch_bounds__(256) void final_k(const float* __restrict__ fuse, const float* __restrict__ ses,
                                               const float* __restrict__ t2, const float* __restrict__ A1,
                                               float* __restrict__ out) {
    int idx = blockIdx.x * 256 + threadIdx.x;
    int bc = idx >> 14;
    out[idx] = sigmoidf(fuse[idx]) * ses[bc] * t2[idx] * A1[idx];
}

// weight transpose+tf32 prep: wt[(tap*64+ic)*64+oc] = tf32(w[(oc*64+ic)*KS2+tap])
__global__ void wprep_k(const float* __restrict__ w, uint32_t* __restrict__ wt, int KS2, int n) {
    int idx = blockIdx.x * 256 + threadIdx.x;
    if (idx >= n) return;
    int oc = idx & 63, t2 = idx >> 6;
    int ic = t2 & 63, tap = t2 >> 6;
    wt[idx] = to_tf32(w[(oc * 64 + ic) * KS2 + tap]);
}

// ---------------- 1x1 convs as SGEMM (f32x2 inner product) -----------------
__global__ __launch_bounds__(256) void g1x1_triple_k(
    const float* __restrict__ x1,
    const float* __restrict__ wf, const float* __restrict__ w1c,
    const float* __restrict__ g1, const float* __restrict__ b1,
    const float* __restrict__ w2c, const float* __restrict__ g2, const float* __restrict__ b2,
    const float* __restrict__ fb, const float* __restrict__ kse1,
    float* __restrict__ ofuse, float* __restrict__ of1, float* __restrict__ of2) {
    __shared__ __align__(16) float As[16][68];
    __shared__ __align__(16) float Bs[16][64];
    int convid = blockIdx.y, b = blockIdx.z, n0 = blockIdx.x * 64;
    const float* W = convid == 0 ? wf : (convid == 1 ? w1c : w2c);
    int tid = threadIdx.x, ty = tid >> 4, tx = tid & 15;
    unsigned long long acc2[4][2] = {};
    for (int k0 = 0; k0 < 128; k0 += 16) {
        __syncthreads();
        {
            int m = tid >> 2, kq = (tid & 3) * 4;
            float4 a4 = *reinterpret_cast<const float4*>(W + m * 128 + k0 + kq);
            As[kq + 0][m] = a4.x; As[kq + 1][m] = a4.y; As[kq + 2][m] = a4.z; As[kq + 3][m] = a4.w;
        }
        #pragma unroll
        for (int l = 0; l < 4; l++) {
            int e = tid + l * 256, kk = e >> 6, n = e & 63;
            Bs[kk][n] = x1[((b * 128 + k0 + kk) << 14) + n0 + n];
        }
        __syncthreads();
        #pragma unroll
        for (int kk = 0; kk < 16; kk++) {
            float4 a = *reinterpret_cast<const float4*>(&As[kk][ty * 4]);
            unsigned long long b01 = *reinterpret_cast<const unsigned long long*>(&Bs[kk][tx * 4]);
            unsigned long long b23 = *reinterpret_cast<const unsigned long long*>(&Bs[kk][tx * 4 + 2]);
            unsigned long long aa0 = pack2(a.x), aa1 = pack2(a.y), aa2 = pack2(a.z), aa3 = pack2(a.w);
            fma2(acc2[0][0], aa0, b01); fma2(acc2[0][1], aa0, b23);
            fma2(acc2[1][0], aa1, b01); fma2(acc2[1][1], aa1, b23);
            fma2(acc2[2][0], aa2, b01); fma2(acc2[2][1], aa2, b23);
            fma2(acc2[3][0], aa3, b01); fma2(acc2[3][1], aa3, b23);
        }
    }
    const float rs = rsqrtf(1.f + EPSF);
    #pragma unroll
    for (int i = 0; i < 4; i++) {
        int c = ty * 4 + i;
        #pragma unroll
        for (int j2 = 0; j2 < 2; j2++) {
            float v0, v1;
            unpack2(acc2[i][j2], v0, v1);
            float vv[2] = {v0, v1};
            #pragma unroll
            for (int u = 0; u < 2; u++) {
                int idx = ((b * 64 + c) << 14) + n0 + tx * 4 + j2 * 2 + u;
                if (convid == 0) {
                    float v = vv[u] + fb[b * 64 + c];
                    ofuse[idx] = v * kse1[idx];
                } else if (convid == 1) {
                    of1[idx] = leakyf(vv[u] * (g1[c] * rs) + b1[c]);
                } else {
                    of2[idx] = leakyf(vv[u] * (g2[c] * rs) + b2[c]);
                }
            }
        }
    }
}

__global__ __launch_bounds__(256) void g1x1_cat_k(
    const float* __restrict__ p1, const float* __restrict__ p2,
    const float* __restrict__ W, const float* __restrict__ gg, const float* __restrict__ bb,
    float* __restrict__ out) {
    __shared__ __align__(16) float As[16][68];
    __shared__ __align__(16) float Bs[16][64];
    int b = blockIdx.z, n0 = blockIdx.x * 64;
    int tid = threadIdx.x, ty = tid >> 4, tx = tid & 15;
    unsigned long long acc2[4][2] = {};
    for (int k0 = 0; k0 < 128; k0 += 16) {
        __syncthreads();
        {
            int m = tid >> 2, kq = (tid & 3) * 4;
            float4 a4 = *reinterpret_cast<const float4*>(W + m * 128 + k0 + kq);
            As[kq + 0][m] = a4.x; As[kq + 1][m] = a4.y; As[kq + 2][m] = a4.z; As[kq + 3][m] = a4.w;
        }
        #pragma unroll
        for (int l = 0; l < 4; l++) {
            int e = tid + l * 256, kk = e >> 6, n = e & 63;
            int ic = k0 + kk;
            const float* src = (ic < 64) ? (p1 + ((b * 64 + ic) << 14))
                                         : (p2 + ((b * 64 + ic - 64) << 14));
            Bs[kk][n] = src[n0 + n];
        }
        __syncthreads();
        #pragma unroll
        for (int kk = 0; kk < 16; kk++) {
            float4 a = *reinterpret_cast<const float4*>(&As[kk][ty * 4]);
            unsigned long long b01 = *reinterpret_cast<const unsigned long long*>(&Bs[kk][tx * 4]);
            unsigned long long b23 = *reinterpret_cast<const unsigned long long*>(&Bs[kk][tx * 4 + 2]);
            unsigned long long aa0 = pack2(a.x), aa1 = pack2(a.y), aa2 = pack2(a.z), aa3 = pack2(a.w);
            fma2(acc2[0][0], aa0, b01); fma2(acc2[0][1], aa0, b23);
            fma2(acc2[1][0], aa1, b01); fma2(acc2[1][1], aa1, b23);
            fma2(acc2[2][0], aa2, b01); fma2(acc2[2][1], aa2, b23);
            fma2(acc2[3][0], aa3, b01); fma2(acc2[3][1], aa3, b23);
        }
    }
    const float rs = rsqrtf(1.f + EPSF);
    #pragma unroll
    for (int i = 0; i < 4; i++) {
        int c = ty * 4 + i;
        float s = gg[c] * rs, beta = bb[c];
        #pragma unroll
        for (int j2 = 0; j2 < 2; j2++) {
            float v0, v1;
            unpack2(acc2[i][j2], v0, v1);
            int idx = ((b * 64 + c) << 14) + n0 + tx * 4 + j2 * 2;
            out[idx]     = leakyf(v0 * s + beta);
            out[idx + 1] = leakyf(v1 * s + beta);
        }
    }
}

// ---------------- conv via tf32 mma.sync, double-buffered -----------------
// smem layout: xs[stage][r][c][8] with plane p at slot 2*((p&3)^q(c)) + (p>>2),
// q(c) = (c>>2)&3.  B-fragment (k=tig, k=tig+4) = one conflict-free LDS.64.
// MODE 0: bnlrelu | 1: sigmoid(bnlrelu) | 2: *aux1 | 3: sigmoid()*aux1*aux2 | 4: +aux1+aux2
template <int KS, int MODE>
__global__ __launch_bounds__(256) void conv_mma_k(
    const float* __restrict__ in, const uint32_t* __restrict__ wt,
    const float* __restrict__ gg, const float* __restrict__ bb,
    const float* __restrict__ aux1, const float* __restrict__ aux2,
    float* __restrict__ out) {
    constexpr int PAD = KS / 2;
    constexpr int SH = 16 + KS - 1, SW = 16 + KS - 1;
    constexpr int NE = 8 * SH * SW;
    constexpr int STG = (NE + 255) / 256;
    __shared__ __align__(16) uint32_t xs[2][SH][SW][8];
    int b = blockIdx.y, tile = blockIdx.x;
    int bx0 = (tile & 7) * 16, by0 = (tile >> 3) * 16;
    int tid = threadIdx.x, wid = tid >> 5, lane = tid & 31;
    int gq = lane >> 2, tig = lane & 3;
    int oc0 = (wid & 3) * 16, xh = (wid >> 2) * 8;

    float acc[16][4];
    #pragma unroll
    for (int y = 0; y < 16; y++)
        #pragma unroll
        for (int j = 0; j < 4; j++) acc[y][j] = 0.f;

    const float* inb = in + ((size_t)b << 20);

    // prologue: chunk 0 -> stage 0
    #pragma unroll
    for (int j = 0; j < STG; j++) {
        int e = tid + j * 256;
        if (e < NE) {
            int i = e / (SH * SW), rem = e - i * (SH * SW);
            int r = rem / SW, c = rem - r * SW;
            int gy = by0 + r - PAD, gx = bx0 + c - PAD;
            float v = 0.f;
            if ((unsigned)gy < 128u && (unsigned)gx < 128u)
                v = inb[(i << 14) + (gy << 7) + gx];
            int slot = ((((i & 3) ^ ((c >> 2) & 3)) << 1) | (i >> 2));
            xs[0][r][c][slot] = to_tf32(v);
        }
    }
    __syncthreads();

    for (int ch = 0; ch < 8; ch++) {
        int cur = ch & 1;
        int ic0 = ch * 8;
        // issue global loads for next chunk (consumed after MMA)
        float sreg[STG];
        if (ch < 7) {
            #pragma unroll
            for (int j = 0; j < STG; j++) {
                int e = tid + j * 256;
                if (e < NE) {
                    int i = e / (SH * SW), rem = e - i * (SH * SW);
                    int r = rem / SW, c = rem - r * SW;
                    int gy = by0 + r - PAD, gx = bx0 + c - PAD;
                    float v = 0.f;
                    if ((unsigned)gy < 128u && (unsigned)gx < 128u)
                        v = inb[((ic0 + 8 + i) << 14) + (gy << 7) + gx];
                    sreg[j] = v;
                }
            }
        }
        // MMA on current stage
        #pragma unroll
        for (int ky = 0; ky < KS; ky++) {
            uint32_t aw[KS][4];
            #pragma unroll
            for (int kx = 0; kx < KS; kx++) {
                int tap = ky * KS + kx;
                const uint32_t* wp = wt + (((tap << 6) + ic0) << 6);
                aw[kx][0] = wp[(tig << 6) + oc0 + gq];
                aw[kx][1] = wp[(tig << 6) + oc0 + 8 + gq];
                aw[kx][2] = wp[((tig + 4) << 6) + oc0 + gq];
                aw[kx][3] = wp[((tig + 4) << 6) + oc0 + 8 + gq];
            }
            #pragma unroll
            for (int kx = 0; kx < KS; kx++) {
                int cc = xh + kx + gq;
                int u = tig ^ ((cc >> 2) & 3);
                #pragma unroll
                for (int y = 0; y < 16; y++) {
                    uint2 bp = *reinterpret_cast<const uint2*>(&xs[cur][y + ky][cc][2 * u]);
                    MMA_TF32(acc[y], aw[kx][0], aw[kx][1], aw[kx][2], aw[kx][3], bp.x, bp.y);
                }
            }
        }
        // store staged regs into other buffer, then sync
        if (ch < 7) {
            #pragma unroll
            for (int j = 0; j < STG; j++) {
                int e = tid + j * 256;
                if (e < NE) {
                    int i = e / (SH * SW), rem = e - i * (SH * SW);
                    int r = rem / SW, c = rem - r * SW;
                    int slot = ((((i & 3) ^ ((c >> 2) & 3)) << 1) | (i >> 2));
                    xs[1 - cur][r][c][slot] = to_tf32(sreg[j]);
                }
            }
            __syncthreads();
        }
    }

    const float rsq = rsqrtf(1.f + EPSF);
    int oc_lo = oc0 + gq, oc_hi = oc0 + 8 + gq;
    float s_lo = gg[oc_lo] * rsq, be_lo = bb[oc_lo];
    float s_hi = gg[oc_hi] * rsq, be_hi = bb[oc_hi];
    int x = bx0 + xh + tig * 2;
    size_t base_lo = ((size_t)(b * 64 + oc_lo) << 14);
    size_t base_hi = ((size_t)(b * 64 + oc_hi) << 14);
    #pragma unroll
    for (int y = 0; y < 16; y++) {
        int yp = by0 + y;
        float v[4] = { acc[y][0] * s_lo + be_lo, acc[y][1] * s_lo + be_lo,
                       acc[y][2] * s_hi + be_hi, acc[y][3] * s_hi + be_hi };
        size_t idx[4] = { base_lo + (yp << 7) + x, base_lo + (yp << 7) + x + 1,
                          base_hi + (yp << 7) + x, base_hi + (yp << 7) + x + 1 };
        #pragma unroll
        for (int j = 0; j < 4; j++) {
            float r = leakyf(v[j]);
            if (MODE == 0) out[idx[j]] = r;
            else if (MODE == 1) out[idx[j]] = sigmoidf(r);
            else if (MODE == 2) out[idx[j]] = r * aux1[idx[j]];
            else if (MODE == 3) out[idx[j]] = sigmoidf(r) * aux1[idx[j]] * aux2[idx[j]];
            else out[idx[j]] = r + aux1[idx[j]] + aux2[idx[j]];
        }
    }
}

// ---------------- per-sample depthwise multi-dilation ---------------------
__global__ __launch_bounds__(256) void multidil_k(
    const float* __restrict__ f2, const float* __restrict__ kk_g,
    const float* __restrict__ kse1, float* __restrict__ out) {
    __shared__ float xs[28][28];
    __shared__ float kk[25];
    int b = blockIdx.z, c = blockIdx.y;
    int txt = blockIdx.x & 7, tyt = blockIdx.x >> 3;
    int bx0 = txt * 16, by0 = tyt * 16;
    int tid = threadIdx.x;
    if (tid < 25) kk[tid] = kk_g[(b * 64 + c) * 25 + tid];
    const float* src = f2 + ((size_t)(b * 64 + c) << 14);
    for (int e = tid; e < 784; e += 256) {
        int r = e / 28, cc = e - r * 28;
        int gy = by0 + r - 6, gx = bx0 + cc - 6;
        float v = 0.f;
        if ((unsigned)gy < 128u && (unsigned)gx < 128u) v = src[(gy << 7) + gx];
        xs[r][cc] = v;
    }
    __syncthreads();
    int py = tid >> 4, px = tid & 15;
    int idx = ((b * 64 + c) << 14) + ((by0 + py) << 7) + bx0 + px;
    float kv = kse1[idx];
    float res;
    if (b == 0) {
        res = xs[py + 6][px + 6];
    } else {
        float a = 0.f;
        #pragma unroll
        for (int d = 1; d <= 3; d++)
            #pragma unroll
            for (int ky = 0; ky < 5; ky++)
                #pragma unroll
                for (int kx = 0; kx < 5; kx++)
                    a += xs[py + 6 + d * (ky - 2)][px + 6 + d * (kx - 2)] * kk[ky * 5 + kx];
        res = a;
    }
    out[idx] = res * kv;
}

// ---------------- host orchestration --------------------------------------
extern "C" void kernel_launch(void* const* d_in, const int* in_sizes, int n_in,
                              void* d_out, int out_size) {
    const float* x1      = (const float*)d_in[0];
    const float* kk      = (const float*)d_in[1];
    const float* conv1_w = (const float*)d_in[2];
    const float* conv1_g = (const float*)d_in[3];
    const float* conv1_b = (const float*)d_in[4];
    const float* conv2_w = (const float*)d_in[5];
    const float* conv2_g = (const float*)d_in[6];
    const float* conv2_b = (const float*)d_in[7];
    const float* conv_w  = (const float*)d_in[8];
    const float* conv_bi = (const float*)d_in[9];
    const float* c0_w    = (const float*)d_in[10];
    const float* c0_g    = (const float*)d_in[11];
    const float* c0_b    = (const float*)d_in[12];
    const float* attc_w  = (const float*)d_in[13];
    const float* attc_g  = (const float*)d_in[14];
    const float* attc_b  = (const float*)d_in[15];
    const float* c05_w   = (const float*)d_in[16];
    const float* c05_g   = (const float*)d_in[17];
    const float* c05_b   = (const float*)d_in[18];
    const float* c0a_w   = (const float*)d_in[19];
    const float* c0a_g   = (const float*)d_in[20];
    const float* c0a_b   = (const float*)d_in[21];
    const float* c0b_w   = (const float*)d_in[22];
    const float* c0b_g   = (const float*)d_in[23];
    const float* c0b_b   = (const float*)d_in[24];
    const float* se_w1   = (const float*)d_in[25];
    const float* se_w2   = (const float*)d_in[26];
    float* outp = (float*)d_out;

    float *kse1, *fuse, *f1, *f2, *eadd, *A1, *out1, *out2, *o2c, *fo2, *eo2, *o2f, *t1, *t2;
    float *va, *fb, *am, *ses;
    uint32_t *wt_c0, *wt_attc, *wt_c0b, *wt_c05;
    cudaGetSymbolAddress((void**)&kse1, g_kse1);
    cudaGetSymbolAddress((void**)&fuse, g_fuse);
    cudaGetSymbolAddress((void**)&f1,   g_f1);
    cudaGetSymbolAddress((void**)&f2,   g_f2);
    cudaGetSymbolAddress((void**)&eadd, g_eadd);
    cudaGetSymbolAddress((void**)&A1,   g_A1);
    cudaGetSymbolAddress((void**)&out1, g_out1);
    cudaGetSymbolAddress((void**)&out2, g_out2);
    cudaGetSymbolAddress((void**)&o2c,  g_o2c);
    cudaGetSymbolAddress((void**)&fo2,  g_fo2);
    cudaGetSymbolAddress((void**)&eo2,  g_eo2);
    cudaGetSymbolAddress((void**)&o2f,  g_o2f);
    cudaGetSymbolAddress((void**)&t1,   g_t1);
    cudaGetSymbolAddress((void**)&t2,   g_t2);
    cudaGetSymbolAddress((void**)&va,   g_va);
    cudaGetSymbolAddress((void**)&fb,   g_fb);
    cudaGetSymbolAddress((void**)&am,   g_am);
    cudaGetSymbolAddress((void**)&ses,  g_ses);
    cudaGetSymbolAddress((void**)&wt_c0,   g_wt_c0);
    cudaGetSymbolAddress((void**)&wt_attc, g_wt_attc);
    cudaGetSymbolAddress((void**)&wt_c0b,  g_wt_c0b);
    cudaGetSymbolAddress((void**)&wt_c05,  g_wt_c05);

    dim3 blk(256);
    dim3 cgrid(64, 8);
    wprep_k<<<(64*64*9 + 255) / 256, blk>>>(c0_w,   wt_c0,   9,  64*64*9);
    wprep_k<<<(64*64*9 + 255) / 256, blk>>>(attc_w, wt_attc, 9,  64*64*9);
    wprep_k<<<(64*64*9 + 255) / 256, blk>>>(c0b_w,  wt_c0b,  9,  64*64*9);
    wprep_k<<<(64*64*25 + 255) / 256, blk>>>(c05_w, wt_c05,  25, 64*64*25);

    rowmean_k<<<1024, blk>>>(x1, va);
    fusebase_k<<<1, 512>>>(va, conv_w, conv_bi, fb);
    kse_k<<<NBIG / 256, blk>>>(kk, kse1);
    g1x1_triple_k<<<dim3(256, 3, 8), blk>>>(x1, conv_w, conv1_w, conv1_g, conv1_b,
                                            conv2_w, conv2_g, conv2_b, fb, kse1,
                                            fuse, f1, f2);
    attmean_k<<<512, blk>>>(fuse, am);
    se_k<<<1, 512>>>(am, se_w1, se_w2, ses);
    conv_mma_k<3, 0><<<cgrid, blk>>>(fuse, wt_c0, c0_g, c0_b, nullptr, nullptr, eadd);
    conv_mma_k<3, 1><<<cgrid, blk>>>(eadd, wt_attc, attc_g, attc_b, nullptr, nullptr, A1);
    conv_mma_k<3, 2><<<cgrid, blk>>>(f1, wt_c0, c0_g, c0_b, kse1, nullptr, out1);
    multidil_k<<<dim3(64, 64, 8), blk>>>(f2, kk, kse1, out2);
    conv_mma_k<5, 0><<<cgrid, blk>>>(out2, wt_c05, c05_g, c05_b, nullptr, nullptr, o2c);
    conv_mma_k<3, 3><<<cgrid, blk>>>(out1, wt_attc, attc_g, attc_b, A1, o2c, fo2);
    conv_mma_k<5, 4><<<cgrid, blk>>>(fo2, wt_c05, c05_g, c05_b, o2c, f2, eo2);
    conv_mma_k<5, 0><<<cgrid, blk>>>(eo2, wt_c05, c05_g, c05_b, nullptr, nullptr, o2f);
    g1x1_cat_k<<<dim3(256, 1, 8), blk>>>(out1, o2f, c0a_w, c0a_g, c0a_b, t1);
    conv_mma_k<3, 0><<<cgrid, blk>>>(t1, wt_c0b, c0b_g, c0b_b, nullptr, nullptr, t2);
    final_k<<<NBIG / 256, blk>>>(fuse, ses, t2, A1, outp);
}